// round 12
// baseline (speedup 1.0000x reference)
#include <cuda_runtime.h>
#include <cuda_bf16.h>
#include <cstdint>

// Problem constants
#define TT 256
#define BB 64
#define EE 512
#define HH 1024
#define VV 10000
#define G4 4096      // 4*H
#define NCTA 128
#define NTHR 512

// y-GEMM (mma.sync) tiling
#define NPAD 10112            // VV padded to multiple of 128 (79 tiles)
#define YST 40960             // bytes per pipeline stage (4 arrays x 128 rows x 80B)
#define YSM_TOTAL (4 * YST)   // 160 KB, 4-stage pipeline

// Scratch (no cudaMalloc allowed): device globals
__device__ float g_xemb[(size_t)TT * BB * EE];            // 33.5 MB
__device__ float g_gx  [(size_t)TT * BB * G4];            // 256  MB
__device__ unsigned g_bar_count;
__device__ unsigned g_bar_phase;
__device__ __nv_bfloat16 g_ah[(size_t)TT * BB * HH];      // hi(all_h)   33.5 MB
__device__ __nv_bfloat16 g_al[(size_t)TT * BB * HH];      // lo(all_h)   33.5 MB
__device__ __nv_bfloat16 g_bh[(size_t)NPAD * HH];         // hi(Wout^T)  20.7 MB
__device__ __nv_bfloat16 g_bl[(size_t)NPAD * HH];         // lo(Wout^T)  20.7 MB

// ===========================================================================
// Helpers
// ===========================================================================
__device__ __forceinline__ uint32_t smem_to_u32(const void* p) {
    uint32_t a;
    asm("{ .reg .u64 t; cvta.to.shared.u64 t, %1; cvt.u32.u64 %0, t; }"
        : "=r"(a) : "l"(p));
    return a;
}
__device__ __forceinline__ void cp16(uint32_t dst, const void* src) {
    asm volatile("cp.async.cg.shared.global [%0], [%1], 16;\n"
                 :: "r"(dst), "l"(src) : "memory");
}
__device__ __forceinline__ void ldsm4(uint32_t& r0, uint32_t& r1,
                                      uint32_t& r2, uint32_t& r3, uint32_t a) {
    asm volatile("ldmatrix.sync.aligned.m8n8.x4.shared.b16 {%0,%1,%2,%3}, [%4];"
                 : "=r"(r0), "=r"(r1), "=r"(r2), "=r"(r3) : "r"(a));
}
__device__ __forceinline__ void hmma(float* d, const uint32_t* a, const uint32_t* b) {
    asm volatile("mma.sync.aligned.m16n8k16.row.col.f32.bf16.bf16.f32 "
                 "{%0,%1,%2,%3}, {%4,%5,%6,%7}, {%8,%9}, {%0,%1,%2,%3};"
                 : "+f"(d[0]), "+f"(d[1]), "+f"(d[2]), "+f"(d[3])
                 : "r"(a[0]), "r"(a[1]), "r"(a[2]), "r"(a[3]),
                   "r"(b[0]), "r"(b[1]));
}

// ---------------------------------------------------------------------------
// Kernel 1: embedding gather
// ---------------------------------------------------------------------------
__global__ void embed_kernel(const int* __restrict__ x, const float* __restrict__ emb) {
    int row = blockIdx.x;
    int idx = x[row];
    const float4* src = (const float4*)(emb + (size_t)idx * EE);
    float4* dst = (float4*)(g_xemb + (size_t)row * EE);
    dst[threadIdx.x] = src[threadIdx.x];
}

// ---------------------------------------------------------------------------
// Kernel 2: gx = x_emb @ W_x + b_g   (fp32 SIMT, unchanged)
// ---------------------------------------------------------------------------
__global__ void __launch_bounds__(256)
gx_gemm_kernel(const float* __restrict__ Wf, const float* __restrict__ Wi,
               const float* __restrict__ Wc, const float* __restrict__ Wo,
               const float* __restrict__ bf, const float* __restrict__ bi,
               const float* __restrict__ bc, const float* __restrict__ bo) {
    __shared__ float As[16][128];
    __shared__ float Bs[16][128];

    const int gate = blockIdx.x >> 3;
    const int col0 = (blockIdx.x & 7) * 128;
    const int m0 = blockIdx.y * 128;
    const float* W = (gate == 0) ? Wf : (gate == 1) ? Wi : (gate == 2) ? Wc : Wo;
    const float* bias = (gate == 0) ? bf : (gate == 1) ? bi : (gate == 2) ? bc : bo;

    const int tid = threadIdx.x;
    const int tm = tid >> 4;
    const int tn = tid & 15;

    float acc[8][8];
#pragma unroll
    for (int a = 0; a < 8; ++a)
#pragma unroll
        for (int b = 0; b < 8; ++b) acc[a][b] = 0.0f;

    for (int k0 = 0; k0 < EE; k0 += 16) {
#pragma unroll
        for (int j = 0; j < 2; ++j) {
            int i = tid * 2 + j;
            int row = i >> 2;
            int kq  = (i & 3) * 4;
            float4 v = *(const float4*)(g_xemb + (size_t)(m0 + row) * EE + k0 + kq);
            As[kq + 0][row] = v.x;
            As[kq + 1][row] = v.y;
            As[kq + 2][row] = v.z;
            As[kq + 3][row] = v.w;
        }
#pragma unroll
        for (int j = 0; j < 2; ++j) {
            int i = tid + j * 256;
            int kk = i >> 5;
            int nq = (i & 31) * 4;
            float4 v = *(const float4*)(W + (size_t)(HH + k0 + kk) * HH + col0 + nq);
            *(float4*)&Bs[kk][nq] = v;
        }
        __syncthreads();

#pragma unroll
        for (int kk = 0; kk < 16; ++kk) {
            float av[8], bv[8];
            *(float4*)(av)     = *(const float4*)&As[kk][tm * 8];
            *(float4*)(av + 4) = *(const float4*)&As[kk][tm * 8 + 4];
            *(float4*)(bv)     = *(const float4*)&Bs[kk][tn * 8];
            *(float4*)(bv + 4) = *(const float4*)&Bs[kk][tn * 8 + 4];
#pragma unroll
            for (int mi = 0; mi < 8; ++mi)
#pragma unroll
                for (int ni = 0; ni < 8; ++ni)
                    acc[mi][ni] += av[mi] * bv[ni];
        }
        __syncthreads();
    }

#pragma unroll
    for (int mi = 0; mi < 8; ++mi) {
        int m = m0 + tm * 8 + mi;
        float* gp = g_gx + (size_t)m * G4 + gate * HH + col0;
#pragma unroll
        for (int ni = 0; ni < 8; ++ni) {
            int n = tn * 8 + ni;
            gp[n] = acc[mi][ni] + bias[col0 + n];
        }
    }
}

// ---------------------------------------------------------------------------
// Kernel 3: persistent LSTM recurrence (unchanged — passed at 15.9ms)
// ---------------------------------------------------------------------------
#define SMEM_FLOATS (43524)
#define SMEM_BYTES  (SMEM_FLOATS * 4)

__device__ __forceinline__ float sigmoidf_(float x) {
    return 1.0f / (1.0f + __expf(-x));
}

__device__ __forceinline__ void slab_load_async(float* dst, const float* hsrc,
                                                int rb, int tid) {
#pragma unroll
    for (int q = 0; q < 8; ++q) {
        int idx = tid + q * NTHR;
        int row = idx >> 8;
        int c4  = idx & 255;
        const float* src = hsrc + (size_t)(rb * 16 + row) * HH + c4 * 4;
        unsigned dsta = (unsigned)__cvta_generic_to_shared(dst + row * HH + c4 * 4);
        asm volatile("cp.async.cg.shared.global [%0], [%1], 16;\n"
                     :: "r"(dsta), "l"(src) : "memory");
    }
}

__device__ __forceinline__ void grid_bar(unsigned target) {
    __syncthreads();
    if (threadIdx.x == 0) {
        __threadfence();
        unsigned old = atomicAdd(&g_bar_count, 1u);
        if (old == NCTA - 1) {
            atomicExch(&g_bar_count, 0u);
            __threadfence();
            atomicAdd(&g_bar_phase, 1u);
        } else {
            while ((int)(*((volatile unsigned*)&g_bar_phase) - target) < 0) {}
            __threadfence();
        }
    }
    __syncthreads();
}

__global__ void __launch_bounds__(NTHR, 1)
lstm_persistent_kernel(const float* __restrict__ h0, const float* __restrict__ c0,
                       const float* __restrict__ Wf, const float* __restrict__ Wi,
                       const float* __restrict__ Wc, const float* __restrict__ Wo,
                       float* __restrict__ all_h, float* __restrict__ all_c) {
    extern __shared__ float smem[];
    float* hs0 = smem;
    float* hs1 = smem + 16384;
    float* sc  = smem + 32768;
    float* gsm = smem + 43008;
    unsigned* shp = (unsigned*)(smem + 43520);

    const int tid = threadIdx.x;
    const int kg  = tid >> 5;
    const int c   = tid & 31;
    const int gate = c >> 3;
    const int jo   = c & 7;
    const int n    = blockIdx.x;
    const int j    = n * 8 + jo;

    const float* Wg = (gate == 0) ? Wf : (gate == 1) ? Wi : (gate == 2) ? Wc : Wo;

    float w[64];
#pragma unroll
    for (int kk = 0; kk < 64; ++kk)
        w[kk] = Wg[(size_t)(kg * 64 + kk) * HH + j];

    if (tid == 0) shp[0] = *((volatile unsigned*)&g_bar_phase);
    __syncthreads();
    const unsigned phase_base = shp[0];

    const int r_ml = tid >> 5;
    const int r_c  = tid & 31;
    const int r_cgl = (r_c >> 3) * HH + n * 8 + (r_c & 7);

    for (int t = 0; t < TT; ++t) {
        const float* hsrc = (t == 0) ? h0 : all_h + (size_t)(t - 1) * BB * HH;
        const float* csrc = (t == 0) ? c0 : all_c + (size_t)(t - 1) * BB * HH;
        float* hdst = all_h + (size_t)t * BB * HH;
        float* cdst = all_c + (size_t)t * BB * HH;

        slab_load_async(hs0, hsrc, 0, tid);
        asm volatile("cp.async.commit_group;\n" ::: "memory");
        asm volatile("cp.async.wait_group 0;\n" ::: "memory");
        __syncthreads();

#pragma unroll 1
        for (int rb = 0; rb < 4; ++rb) {
            float* cur = (rb & 1) ? hs1 : hs0;
            float* nxt = (rb & 1) ? hs0 : hs1;
            if (rb < 3) {
                slab_load_async(nxt, hsrc, rb + 1, tid);
                asm volatile("cp.async.commit_group;\n" ::: "memory");
            }

            const float* hbase = cur + kg * 64;
#pragma unroll 1
            for (int mi = 0; mi < 16; ++mi) {
                const float4* h4 = (const float4*)(hbase + mi * HH);
                float a0 = 0.f, a1 = 0.f, a2 = 0.f, a3 = 0.f;
#pragma unroll
                for (int q = 0; q < 16; ++q) {
                    float4 v = h4[q];
                    a0 = fmaf(v.x, w[4 * q + 0], a0);
                    a1 = fmaf(v.y, w[4 * q + 1], a1);
                    a2 = fmaf(v.z, w[4 * q + 2], a2);
                    a3 = fmaf(v.w, w[4 * q + 3], a3);
                }
                sc[(mi * 32 + c) * 20 + kg] = (a0 + a1) + (a2 + a3);
            }
            __syncthreads();

            {
                const float* p = sc + (r_ml * 32 + r_c) * 20;
                float4 s0 = *(const float4*)(p);
                float4 s1 = *(const float4*)(p + 4);
                float4 s2 = *(const float4*)(p + 8);
                float4 s3 = *(const float4*)(p + 12);
                float s = ((s0.x + s0.y) + (s0.z + s0.w))
                        + ((s1.x + s1.y) + (s1.z + s1.w))
                        + ((s2.x + s2.y) + (s2.z + s2.w))
                        + ((s3.x + s3.y) + (s3.z + s3.w));
                int mrow = rb * 16 + r_ml;
                s += g_gx[((size_t)t * BB + mrow) * G4 + r_cgl];
                gsm[r_ml * 32 + r_c] = s;
            }
            __syncthreads();

            if (tid < 128) {
                int ml = tid >> 3;
                int jj = tid & 7;
                int mrow = rb * 16 + ml;
                const float* g = gsm + ml * 32;
                float f  = sigmoidf_(g[jj]);
                float ii = sigmoidf_(g[8 + jj]);
                float cd = tanhf(g[16 + jj]);
                float o  = sigmoidf_(g[24 + jj]);
                size_t off = (size_t)mrow * HH + n * 8 + jj;
                float cn = f * csrc[off] + ii * cd;
                cdst[off] = cn;
                hdst[off] = o * tanhf(cn);
            }
            if (rb < 3) asm volatile("cp.async.wait_group 0;\n" ::: "memory");
            __syncthreads();
        }

        grid_bar(phase_base + (unsigned)t + 1u);
    }
}

// ---------------------------------------------------------------------------
// Kernel 4a: split all_h into bf16 hi/lo
// ---------------------------------------------------------------------------
__global__ void __launch_bounds__(256)
hsplit_kernel(const float* __restrict__ all_h) {
    size_t i = (size_t)blockIdx.x * 256 + threadIdx.x;
    float v = all_h[i];
    __nv_bfloat16 h = __float2bfloat16(v);
    g_ah[i] = h;
    g_al[i] = __float2bfloat16(v - __bfloat162float(h));
}

// ---------------------------------------------------------------------------
// Kernel 4b: transpose + split Wout [K][V] -> Bh/Bl [NPAD][K] bf16 (zero-pad)
// ---------------------------------------------------------------------------
__global__ void __launch_bounds__(256)
wsplit_kernel(const float* __restrict__ W) {
    __shared__ float t[32][33];
    int k0 = blockIdx.x * 32, n0 = blockIdx.y * 32;
    int tx = threadIdx.x, ty = threadIdx.y;
#pragma unroll
    for (int j = 0; j < 4; ++j) {
        int k = k0 + ty + j * 8, n = n0 + tx;
        t[ty + j * 8][tx] = (n < VV) ? W[(size_t)k * VV + n] : 0.0f;
    }
    __syncthreads();
#pragma unroll
    for (int j = 0; j < 4; ++j) {
        int n = n0 + ty + j * 8, k = k0 + tx;
        float v = t[tx][ty + j * 8];
        __nv_bfloat16 h = __float2bfloat16(v);
        g_bh[(size_t)n * HH + k] = h;
        g_bl[(size_t)n * HH + k] = __float2bfloat16(v - __bfloat162float(h));
    }
}

// ---------------------------------------------------------------------------
// Kernel 5: mma.sync y-GEMM  Y = Ah@Bh^T + Ah@Bl^T + Al@Bh^T + bias
// 128x128 tile/CTA, 256 thr (8 warps, 2x4), K staged 32, 4-stage cp.async.
// smem stage layout (80B padded rows for conflict-free ldmatrix):
//   Ah @+0, Al @+10240, Bh @+20480, Bl @+30720  (each 128 rows x 80B)
// ---------------------------------------------------------------------------
__device__ __forceinline__ void y_fill(uint32_t sb, int stage, int m0, int n0,
                                       int kb, int tid) {
    uint32_t tb = sb + stage * YST;
#pragma unroll
    for (int i = 0; i < 8; ++i) {
        int idx = tid + i * 256;          // 0..2047
        int arr = idx >> 9;               // 0..3 (uniform per i)
        int row = (idx & 511) >> 2;       // 0..127
        int ch  = idx & 3;                // 16B chunk (8 bf16)
        uint32_t dst = tb + arr * 10240 + row * 80 + ch * 16;
        size_t goff = (size_t)(((arr < 2) ? m0 : n0) + row) * HH + kb + ch * 8;
        const __nv_bfloat16* src =
            (arr == 0) ? g_ah : (arr == 1) ? g_al : (arr == 2) ? g_bh : g_bl;
        cp16(dst, src + goff);
    }
    asm volatile("cp.async.commit_group;" ::: "memory");
}

__global__ void __launch_bounds__(256, 1)
ysync_kernel(const float* __restrict__ bout, float* __restrict__ Y) {
    extern __shared__ char ysm[];
    uint32_t sb = smem_to_u32(ysm);
    const int tid = threadIdx.x;
    const int lane = tid & 31;
    const int wid = tid >> 5;
    const int wm = wid & 1;               // m-warp (64 rows)
    const int wn = wid >> 1;              // n-warp (32 cols)
    const int n0 = blockIdx.x * 128;
    const int m0 = blockIdx.y * 128;

    // ldmatrix lane addressing: sub selects which 8x8 matrix this lane feeds
    const int lrow = lane & 7;
    const int sub  = lane >> 3;           // 0..3
    const int r16  = (sub & 1) * 8 + lrow;   // row within 16-row tile
    const int kby  = (sub >> 1) * 16;        // byte offset within k16

    float acc[4][4][4];
#pragma unroll
    for (int a = 0; a < 4; ++a)
#pragma unroll
        for (int b = 0; b < 4; ++b)
#pragma unroll
            for (int d = 0; d < 4; ++d) acc[a][b][d] = 0.0f;

    y_fill(sb, 0, m0, n0, 0,  tid);
    y_fill(sb, 1, m0, n0, 32, tid);
    y_fill(sb, 2, m0, n0, 64, tid);

#pragma unroll 1
    for (int it = 0; it < 32; ++it) {
        if (it < 30)       asm volatile("cp.async.wait_group 2;" ::: "memory");
        else if (it == 30) asm volatile("cp.async.wait_group 1;" ::: "memory");
        else               asm volatile("cp.async.wait_group 0;" ::: "memory");
        __syncthreads();

        uint32_t tb = sb + (it & 3) * YST;

#pragma unroll
        for (int ks = 0; ks < 2; ++ks) {
            uint32_t ah[4][4], al[4][4], bh[4][2], bl[4][2];
#pragma unroll
            for (int mf = 0; mf < 4; ++mf) {
                uint32_t ab = tb + (uint32_t)(wm * 64 + mf * 16 + r16) * 80
                            + ks * 32 + kby;
                ldsm4(ah[mf][0], ah[mf][1], ah[mf][2], ah[mf][3], ab);
                ldsm4(al[mf][0], al[mf][1], al[mf][2], al[mf][3], ab + 10240);
            }
#pragma unroll
            for (int nf = 0; nf < 2; ++nf) {
                uint32_t bb = tb + 20480
                            + (uint32_t)(wn * 32 + nf * 16 + r16) * 80
                            + ks * 32 + kby;
                uint32_t r0, r1, r2, r3;
                ldsm4(r0, r1, r2, r3, bb);
                bh[2 * nf][0] = r0;  bh[2 * nf][1] = r2;
                bh[2 * nf + 1][0] = r1;  bh[2 * nf + 1][1] = r3;
                ldsm4(r0, r1, r2, r3, bb + 10240);
                bl[2 * nf][0] = r0;  bl[2 * nf][1] = r2;
                bl[2 * nf + 1][0] = r1;  bl[2 * nf + 1][1] = r3;
            }
#pragma unroll
            for (int mf = 0; mf < 4; ++mf)
#pragma unroll
                for (int nb = 0; nb < 4; ++nb) {
                    hmma(acc[mf][nb], ah[mf], bh[nb]);
                    hmma(acc[mf][nb], ah[mf], bl[nb]);
                    hmma(acc[mf][nb], al[mf], bh[nb]);
                }
        }

        if (it + 3 < 32) y_fill(sb, (it + 3) & 3, m0, n0, (it + 3) * 32, tid);
    }

    // Epilogue: direct stores + bias
    const int g  = lane >> 2;
    const int i2 = (lane & 3) * 2;
#pragma unroll
    for (int mf = 0; mf < 4; ++mf) {
        int r0 = m0 + wm * 64 + mf * 16 + g;
#pragma unroll
        for (int nb = 0; nb < 4; ++nb) {
            int cc = n0 + wn * 32 + nb * 8 + i2;
            if (cc < VV) {
                float b0 = bout[cc], b1 = bout[cc + 1];
                float2 v0 = make_float2(acc[mf][nb][0] + b0, acc[mf][nb][1] + b1);
                *(float2*)(Y + (size_t)r0 * VV + cc) = v0;
                float2 v1 = make_float2(acc[mf][nb][2] + b0, acc[mf][nb][3] + b1);
                *(float2*)(Y + (size_t)(r0 + 8) * VV + cc) = v1;
            }
        }
    }
}

// ---------------------------------------------------------------------------
// Launch
// ---------------------------------------------------------------------------
extern "C" void kernel_launch(void* const* d_in, const int* in_sizes, int n_in,
                              void* d_out, int out_size) {
    const int*   x     = (const int*)d_in[0];
    const float* h0    = (const float*)d_in[1];
    const float* c0    = (const float*)d_in[2];
    const float* emb   = (const float*)d_in[3];
    const float* Wf_w  = (const float*)d_in[4];
    const float* Wf_b  = (const float*)d_in[5];
    const float* Wi_w  = (const float*)d_in[6];
    const float* Wi_b  = (const float*)d_in[7];
    const float* Wc_w  = (const float*)d_in[8];
    const float* Wc_b  = (const float*)d_in[9];
    const float* Wo_w  = (const float*)d_in[10];
    const float* Wo_b  = (const float*)d_in[11];
    const float* Woutw = (const float*)d_in[12];
    const float* Woutb = (const float*)d_in[13];

    float* out   = (float*)d_out;
    float* all_h = out;
    float* all_c = out + (size_t)TT * BB * HH;
    float* all_y = out + (size_t)2 * TT * BB * HH;

    cudaFuncSetAttribute(lstm_persistent_kernel,
                         cudaFuncAttributeMaxDynamicSharedMemorySize, SMEM_BYTES);
    cudaFuncSetAttribute(ysync_kernel,
                         cudaFuncAttributeMaxDynamicSharedMemorySize, YSM_TOTAL);

    // 1) gather embeddings
    embed_kernel<<<TT * BB, 128>>>(x, emb);

    // 2) hoisted x-projection + bias
    dim3 gxg(32, (TT * BB) / 128);
    gx_gemm_kernel<<<gxg, 256>>>(Wf_w, Wi_w, Wc_w, Wo_w, Wf_b, Wi_b, Wc_b, Wo_b);

    // 2b) Wout transpose + bf16 hi/lo split (independent of recurrence)
    dim3 wsg(HH / 32, NPAD / 32);
    wsplit_kernel<<<wsg, dim3(32, 8)>>>(Woutw);

    // 3) recurrence (persistent, fp32)
    lstm_persistent_kernel<<<NCTA, NTHR, SMEM_BYTES>>>(h0, c0,
                                                       Wf_w, Wi_w, Wc_w, Wo_w,
                                                       all_h, all_c);

    // 4) split all_h into bf16 hi/lo
    hsplit_kernel<<<(TT * BB * HH) / 256, 256>>>(all_h);

    // 5) tensor-core y-projection (mma.sync bf16, 3-pass hi/lo)
    dim3 yg(NPAD / 128, (TT * BB) / 128);   // 79 x 128
    ysync_kernel<<<yg, 256, YSM_TOTAL>>>(Woutb, all_y);
}

// round 14
// speedup vs baseline: 1.9195x; 1.9195x over previous
#include <cuda_runtime.h>
#include <cuda_bf16.h>
#include <cuda_fp16.h>
#include <cstdint>

// Problem constants
#define TT 256
#define BB 64
#define EE 512
#define HH 1024
#define VV 10000
#define G4 4096      // 4*H
#define NCTA 128
#define NTHR 512

// y-GEMM (mma.sync fp16 1-pass) tiling
#define NPAD2 10240           // VV padded to multiple of 256 (40 tiles)
#define YST 30720             // bytes/stage: A 128x80 + B 256x80
#define YSM_TOTAL (4 * YST)   // 120 KB, 4-stage pipeline

// Scratch (no cudaMalloc allowed): device globals
__device__ float g_xemb[(size_t)TT * BB * EE];            // 33.5 MB
__device__ float g_gx  [(size_t)TT * BB * G4];            // 256  MB
__device__ unsigned g_bar_count;
__device__ unsigned g_bar_phase;
__device__ __half g_ah[(size_t)TT * BB * HH];             // fp16(all_h)  33.5 MB
__device__ __half g_bh[(size_t)NPAD2 * HH];               // fp16(Wout^T) 21 MB

// ===========================================================================
// Helpers
// ===========================================================================
__device__ __forceinline__ uint32_t smem_to_u32(const void* p) {
    uint32_t a;
    asm("{ .reg .u64 t; cvta.to.shared.u64 t, %1; cvt.u32.u64 %0, t; }"
        : "=r"(a) : "l"(p));
    return a;
}
__device__ __forceinline__ void cp16(uint32_t dst, const void* src) {
    asm volatile("cp.async.cg.shared.global [%0], [%1], 16;\n"
                 :: "r"(dst), "l"(src) : "memory");
}
__device__ __forceinline__ void ldsm4(uint32_t& r0, uint32_t& r1,
                                      uint32_t& r2, uint32_t& r3, uint32_t a) {
    asm volatile("ldmatrix.sync.aligned.m8n8.x4.shared.b16 {%0,%1,%2,%3}, [%4];"
                 : "=r"(r0), "=r"(r1), "=r"(r2), "=r"(r3) : "r"(a));
}
__device__ __forceinline__ void hmma16(float* d, const uint32_t* a, const uint32_t* b) {
    asm volatile("mma.sync.aligned.m16n8k16.row.col.f32.f16.f16.f32 "
                 "{%0,%1,%2,%3}, {%4,%5,%6,%7}, {%8,%9}, {%0,%1,%2,%3};"
                 : "+f"(d[0]), "+f"(d[1]), "+f"(d[2]), "+f"(d[3])
                 : "r"(a[0]), "r"(a[1]), "r"(a[2]), "r"(a[3]),
                   "r"(b[0]), "r"(b[1]));
}

// ---------------------------------------------------------------------------
// Kernel 1: embedding gather
// ---------------------------------------------------------------------------
__global__ void embed_kernel(const int* __restrict__ x, const float* __restrict__ emb) {
    int row = blockIdx.x;
    int idx = x[row];
    const float4* src = (const float4*)(emb + (size_t)idx * EE);
    float4* dst = (float4*)(g_xemb + (size_t)row * EE);
    dst[threadIdx.x] = src[threadIdx.x];
}

// ---------------------------------------------------------------------------
// Kernel 2: gx = x_emb @ W_x + b_g   (fp32 SIMT, proven)
// ---------------------------------------------------------------------------
__global__ void __launch_bounds__(256)
gx_gemm_kernel(const float* __restrict__ Wf, const float* __restrict__ Wi,
               const float* __restrict__ Wc, const float* __restrict__ Wo,
               const float* __restrict__ bf, const float* __restrict__ bi,
               const float* __restrict__ bc, const float* __restrict__ bo) {
    __shared__ float As[16][128];
    __shared__ float Bs[16][128];

    const int gate = blockIdx.x >> 3;
    const int col0 = (blockIdx.x & 7) * 128;
    const int m0 = blockIdx.y * 128;
    const float* W = (gate == 0) ? Wf : (gate == 1) ? Wi : (gate == 2) ? Wc : Wo;
    const float* bias = (gate == 0) ? bf : (gate == 1) ? bi : (gate == 2) ? bc : bo;

    const int tid = threadIdx.x;
    const int tm = tid >> 4;
    const int tn = tid & 15;

    float acc[8][8];
#pragma unroll
    for (int a = 0; a < 8; ++a)
#pragma unroll
        for (int b = 0; b < 8; ++b) acc[a][b] = 0.0f;

    for (int k0 = 0; k0 < EE; k0 += 16) {
#pragma unroll
        for (int j = 0; j < 2; ++j) {
            int i = tid * 2 + j;
            int row = i >> 2;
            int kq  = (i & 3) * 4;
            float4 v = *(const float4*)(g_xemb + (size_t)(m0 + row) * EE + k0 + kq);
            As[kq + 0][row] = v.x;
            As[kq + 1][row] = v.y;
            As[kq + 2][row] = v.z;
            As[kq + 3][row] = v.w;
        }
#pragma unroll
        for (int j = 0; j < 2; ++j) {
            int i = tid + j * 256;
            int kk = i >> 5;
            int nq = (i & 31) * 4;
            float4 v = *(const float4*)(W + (size_t)(HH + k0 + kk) * HH + col0 + nq);
            *(float4*)&Bs[kk][nq] = v;
        }
        __syncthreads();

#pragma unroll
        for (int kk = 0; kk < 16; ++kk) {
            float av[8], bv[8];
            *(float4*)(av)     = *(const float4*)&As[kk][tm * 8];
            *(float4*)(av + 4) = *(const float4*)&As[kk][tm * 8 + 4];
            *(float4*)(bv)     = *(const float4*)&Bs[kk][tn * 8];
            *(float4*)(bv + 4) = *(const float4*)&Bs[kk][tn * 8 + 4];
#pragma unroll
            for (int mi = 0; mi < 8; ++mi)
#pragma unroll
                for (int ni = 0; ni < 8; ++ni)
                    acc[mi][ni] += av[mi] * bv[ni];
        }
        __syncthreads();
    }

#pragma unroll
    for (int mi = 0; mi < 8; ++mi) {
        int m = m0 + tm * 8 + mi;
        float* gp = g_gx + (size_t)m * G4 + gate * HH + col0;
#pragma unroll
        for (int ni = 0; ni < 8; ++ni) {
            int n = tn * 8 + ni;
            gp[n] = acc[mi][ni] + bias[col0 + n];
        }
    }
}

// ---------------------------------------------------------------------------
// Kernel 3: persistent LSTM recurrence (proven at 15.9ms total — unchanged)
// ---------------------------------------------------------------------------
#define SMEM_FLOATS (43524)
#define SMEM_BYTES  (SMEM_FLOATS * 4)

__device__ __forceinline__ float sigmoidf_(float x) {
    return 1.0f / (1.0f + __expf(-x));
}

__device__ __forceinline__ void slab_load_async(float* dst, const float* hsrc,
                                                int rb, int tid) {
#pragma unroll
    for (int q = 0; q < 8; ++q) {
        int idx = tid + q * NTHR;
        int row = idx >> 8;
        int c4  = idx & 255;
        const float* src = hsrc + (size_t)(rb * 16 + row) * HH + c4 * 4;
        unsigned dsta = (unsigned)__cvta_generic_to_shared(dst + row * HH + c4 * 4);
        asm volatile("cp.async.cg.shared.global [%0], [%1], 16;\n"
                     :: "r"(dsta), "l"(src) : "memory");
    }
}

__device__ __forceinline__ void grid_bar(unsigned target) {
    __syncthreads();
    if (threadIdx.x == 0) {
        __threadfence();
        unsigned old = atomicAdd(&g_bar_count, 1u);
        if (old == NCTA - 1) {
            atomicExch(&g_bar_count, 0u);
            __threadfence();
            atomicAdd(&g_bar_phase, 1u);
        } else {
            while ((int)(*((volatile unsigned*)&g_bar_phase) - target) < 0) {}
            __threadfence();
        }
    }
    __syncthreads();
}

__global__ void __launch_bounds__(NTHR, 1)
lstm_persistent_kernel(const float* __restrict__ h0, const float* __restrict__ c0,
                       const float* __restrict__ Wf, const float* __restrict__ Wi,
                       const float* __restrict__ Wc, const float* __restrict__ Wo,
                       float* __restrict__ all_h, float* __restrict__ all_c) {
    extern __shared__ float smem[];
    float* hs0 = smem;
    float* hs1 = smem + 16384;
    float* sc  = smem + 32768;
    float* gsm = smem + 43008;
    unsigned* shp = (unsigned*)(smem + 43520);

    const int tid = threadIdx.x;
    const int kg  = tid >> 5;
    const int c   = tid & 31;
    const int gate = c >> 3;
    const int jo   = c & 7;
    const int n    = blockIdx.x;
    const int j    = n * 8 + jo;

    const float* Wg = (gate == 0) ? Wf : (gate == 1) ? Wi : (gate == 2) ? Wc : Wo;

    float w[64];
#pragma unroll
    for (int kk = 0; kk < 64; ++kk)
        w[kk] = Wg[(size_t)(kg * 64 + kk) * HH + j];

    if (tid == 0) shp[0] = *((volatile unsigned*)&g_bar_phase);
    __syncthreads();
    const unsigned phase_base = shp[0];

    const int r_ml = tid >> 5;
    const int r_c  = tid & 31;
    const int r_cgl = (r_c >> 3) * HH + n * 8 + (r_c & 7);

    for (int t = 0; t < TT; ++t) {
        const float* hsrc = (t == 0) ? h0 : all_h + (size_t)(t - 1) * BB * HH;
        const float* csrc = (t == 0) ? c0 : all_c + (size_t)(t - 1) * BB * HH;
        float* hdst = all_h + (size_t)t * BB * HH;
        float* cdst = all_c + (size_t)t * BB * HH;

        slab_load_async(hs0, hsrc, 0, tid);
        asm volatile("cp.async.commit_group;\n" ::: "memory");
        asm volatile("cp.async.wait_group 0;\n" ::: "memory");
        __syncthreads();

#pragma unroll 1
        for (int rb = 0; rb < 4; ++rb) {
            float* cur = (rb & 1) ? hs1 : hs0;
            float* nxt = (rb & 1) ? hs0 : hs1;
            if (rb < 3) {
                slab_load_async(nxt, hsrc, rb + 1, tid);
                asm volatile("cp.async.commit_group;\n" ::: "memory");
            }

            const float* hbase = cur + kg * 64;
#pragma unroll 1
            for (int mi = 0; mi < 16; ++mi) {
                const float4* h4 = (const float4*)(hbase + mi * HH);
                float a0 = 0.f, a1 = 0.f, a2 = 0.f, a3 = 0.f;
#pragma unroll
                for (int q = 0; q < 16; ++q) {
                    float4 v = h4[q];
                    a0 = fmaf(v.x, w[4 * q + 0], a0);
                    a1 = fmaf(v.y, w[4 * q + 1], a1);
                    a2 = fmaf(v.z, w[4 * q + 2], a2);
                    a3 = fmaf(v.w, w[4 * q + 3], a3);
                }
                sc[(mi * 32 + c) * 20 + kg] = (a0 + a1) + (a2 + a3);
            }
            __syncthreads();

            {
                const float* p = sc + (r_ml * 32 + r_c) * 20;
                float4 s0 = *(const float4*)(p);
                float4 s1 = *(const float4*)(p + 4);
                float4 s2 = *(const float4*)(p + 8);
                float4 s3 = *(const float4*)(p + 12);
                float s = ((s0.x + s0.y) + (s0.z + s0.w))
                        + ((s1.x + s1.y) + (s1.z + s1.w))
                        + ((s2.x + s2.y) + (s2.z + s2.w))
                        + ((s3.x + s3.y) + (s3.z + s3.w));
                int mrow = rb * 16 + r_ml;
                s += g_gx[((size_t)t * BB + mrow) * G4 + r_cgl];
                gsm[r_ml * 32 + r_c] = s;
            }
            __syncthreads();

            if (tid < 128) {
                int ml = tid >> 3;
                int jj = tid & 7;
                int mrow = rb * 16 + ml;
                const float* g = gsm + ml * 32;
                float f  = sigmoidf_(g[jj]);
                float ii = sigmoidf_(g[8 + jj]);
                float cd = tanhf(g[16 + jj]);
                float o  = sigmoidf_(g[24 + jj]);
                size_t off = (size_t)mrow * HH + n * 8 + jj;
                float cn = f * csrc[off] + ii * cd;
                cdst[off] = cn;
                hdst[off] = o * tanhf(cn);
            }
            if (rb < 3) asm volatile("cp.async.wait_group 0;\n" ::: "memory");
            __syncthreads();
        }

        grid_bar(phase_base + (unsigned)t + 1u);
    }
}

// ---------------------------------------------------------------------------
// Kernel 4a: convert all_h -> fp16
// ---------------------------------------------------------------------------
__global__ void __launch_bounds__(256)
hconv_kernel(const float* __restrict__ all_h) {
    size_t i = (size_t)blockIdx.x * 256 + threadIdx.x;
    g_ah[i] = __float2half(all_h[i]);
}

// ---------------------------------------------------------------------------
// Kernel 4b: transpose + convert Wout [K][V] -> g_bh [NPAD2][K] fp16 (zero-pad)
// ---------------------------------------------------------------------------
__global__ void __launch_bounds__(256)
wconv_kernel(const float* __restrict__ W) {
    __shared__ float t[32][33];
    int k0 = blockIdx.x * 32, n0 = blockIdx.y * 32;
    int tx = threadIdx.x, ty = threadIdx.y;
#pragma unroll
    for (int j = 0; j < 4; ++j) {
        int k = k0 + ty + j * 8, n = n0 + tx;
        t[ty + j * 8][tx] = (n < VV) ? W[(size_t)k * VV + n] : 0.0f;
    }
    __syncthreads();
#pragma unroll
    for (int j = 0; j < 4; ++j) {
        int n = n0 + ty + j * 8, k = k0 + tx;
        g_bh[(size_t)n * HH + k] = __float2half(t[tx][ty + j * 8]);
    }
}

// ---------------------------------------------------------------------------
// Kernel 5: fp16 1-pass mma.sync y-GEMM  Y = A@B^T + bias
// 128x256 tile/CTA, 512 thr (16 warps: wm 2 x wn 8), K staged 32, 4 stages.
// Stage layout (80B padded rows, conflict-free ldmatrix):
//   A @+0 (128 rows x 80B), B @+10240 (256 rows x 80B)
// ---------------------------------------------------------------------------
__device__ __forceinline__ void y_fill(uint32_t sb, int stage, int m0, int n0,
                                       int kb, int tid) {
    uint32_t tb = sb + stage * YST;
    // i = 0: A rows (512 cp16);  i = 1,2: B rows (1024 cp16)
    {
        int row = tid >> 2;               // 0..127
        int ch  = tid & 3;
        cp16(tb + row * 80 + ch * 16,
             g_ah + (size_t)(m0 + row) * HH + kb + ch * 8);
    }
#pragma unroll
    for (int i = 0; i < 2; ++i) {
        int idx = tid + i * 512;          // 0..1023
        int row = idx >> 2;               // 0..255
        int ch  = idx & 3;
        cp16(tb + 10240 + row * 80 + ch * 16,
             g_bh + (size_t)(n0 + row) * HH + kb + ch * 8);
    }
    asm volatile("cp.async.commit_group;" ::: "memory");
}

__global__ void __launch_bounds__(512, 1)
ysync_kernel(const float* __restrict__ bout, float* __restrict__ Y) {
    extern __shared__ char ysm[];
    uint32_t sb = smem_to_u32(ysm);
    const int tid = threadIdx.x;
    const int lane = tid & 31;
    const int wid = tid >> 5;
    const int wm = wid & 1;               // m-warp (64 rows)
    const int wn = wid >> 1;              // n-warp 0..7 (32 cols each)
    const int n0 = blockIdx.x * 256;
    const int m0 = blockIdx.y * 128;

    // ldmatrix lane addressing (validated in R12 run)
    const int lrow = lane & 7;
    const int sub  = lane >> 3;           // 0..3
    const int r16  = (sub & 1) * 8 + lrow;
    const int kby  = (sub >> 1) * 16;

    float acc[4][4][4];
#pragma unroll
    for (int a = 0; a < 4; ++a)
#pragma unroll
        for (int b = 0; b < 4; ++b)
#pragma unroll
            for (int d = 0; d < 4; ++d) acc[a][b][d] = 0.0f;

    y_fill(sb, 0, m0, n0, 0,  tid);
    y_fill(sb, 1, m0, n0, 32, tid);
    y_fill(sb, 2, m0, n0, 64, tid);

#pragma unroll 1
    for (int it = 0; it < 32; ++it) {
        if (it < 30)       asm volatile("cp.async.wait_group 2;" ::: "memory");
        else if (it == 30) asm volatile("cp.async.wait_group 1;" ::: "memory");
        else               asm volatile("cp.async.wait_group 0;" ::: "memory");
        __syncthreads();

        uint32_t tb = sb + (it & 3) * YST;

#pragma unroll
        for (int ks = 0; ks < 2; ++ks) {
            uint32_t ah[4][4], bf[4][2];
#pragma unroll
            for (int mf = 0; mf < 4; ++mf) {
                uint32_t ab = tb + (uint32_t)(wm * 64 + mf * 16 + r16) * 80
                            + ks * 32 + kby;
                ldsm4(ah[mf][0], ah[mf][1], ah[mf][2], ah[mf][3], ab);
            }
#pragma unroll
            for (int nf = 0; nf < 2; ++nf) {
                uint32_t bb = tb + 10240
                            + (uint32_t)(wn * 32 + nf * 16 + r16) * 80
                            + ks * 32 + kby;
                uint32_t r0, r1, r2, r3;
                ldsm4(r0, r1, r2, r3, bb);
                bf[2 * nf][0] = r0;      bf[2 * nf][1] = r2;
                bf[2 * nf + 1][0] = r1;  bf[2 * nf + 1][1] = r3;
            }
#pragma unroll
            for (int mf = 0; mf < 4; ++mf)
#pragma unroll
                for (int nb = 0; nb < 4; ++nb)
                    hmma16(acc[mf][nb], ah[mf], bf[nb]);
        }

        if (it + 3 < 32) y_fill(sb, (it + 3) & 3, m0, n0, (it + 3) * 32, tid);
    }

    // Epilogue: direct stores + bias
    const int g  = lane >> 2;
    const int i2 = (lane & 3) * 2;
#pragma unroll
    for (int mf = 0; mf < 4; ++mf) {
        int r0 = m0 + wm * 64 + mf * 16 + g;
#pragma unroll
        for (int nb = 0; nb < 4; ++nb) {
            int cc = n0 + wn * 32 + nb * 8 + i2;
            if (cc < VV) {
                float b0 = bout[cc], b1 = bout[cc + 1];
                float2 v0 = make_float2(acc[mf][nb][0] + b0, acc[mf][nb][1] + b1);
                *(float2*)(Y + (size_t)r0 * VV + cc) = v0;
                float2 v1 = make_float2(acc[mf][nb][2] + b0, acc[mf][nb][3] + b1);
                *(float2*)(Y + (size_t)(r0 + 8) * VV + cc) = v1;
            }
        }
    }
}

// ---------------------------------------------------------------------------
// Launch
// ---------------------------------------------------------------------------
extern "C" void kernel_launch(void* const* d_in, const int* in_sizes, int n_in,
                              void* d_out, int out_size) {
    const int*   x     = (const int*)d_in[0];
    const float* h0    = (const float*)d_in[1];
    const float* c0    = (const float*)d_in[2];
    const float* emb   = (const float*)d_in[3];
    const float* Wf_w  = (const float*)d_in[4];
    const float* Wf_b  = (const float*)d_in[5];
    const float* Wi_w  = (const float*)d_in[6];
    const float* Wi_b  = (const float*)d_in[7];
    const float* Wc_w  = (const float*)d_in[8];
    const float* Wc_b  = (const float*)d_in[9];
    const float* Wo_w  = (const float*)d_in[10];
    const float* Wo_b  = (const float*)d_in[11];
    const float* Woutw = (const float*)d_in[12];
    const float* Woutb = (const float*)d_in[13];

    float* out   = (float*)d_out;
    float* all_h = out;
    float* all_c = out + (size_t)TT * BB * HH;
    float* all_y = out + (size_t)2 * TT * BB * HH;

    cudaFuncSetAttribute(lstm_persistent_kernel,
                         cudaFuncAttributeMaxDynamicSharedMemorySize, SMEM_BYTES);
    cudaFuncSetAttribute(ysync_kernel,
                         cudaFuncAttributeMaxDynamicSharedMemorySize, YSM_TOTAL);

    // 1) gather embeddings
    embed_kernel<<<TT * BB, 128>>>(x, emb);

    // 2) hoisted x-projection + bias
    dim3 gxg(32, (TT * BB) / 128);
    gx_gemm_kernel<<<gxg, 256>>>(Wf_w, Wi_w, Wc_w, Wo_w, Wf_b, Wi_b, Wc_b, Wo_b);

    // 2b) Wout transpose + fp16 convert (independent of recurrence)
    dim3 wsg(HH / 32, NPAD2 / 32);
    wconv_kernel<<<wsg, dim3(32, 8)>>>(Woutw);

    // 3) recurrence (persistent, fp32 — proven)
    lstm_persistent_kernel<<<NCTA, NTHR, SMEM_BYTES>>>(h0, c0,
                                                       Wf_w, Wi_w, Wc_w, Wo_w,
                                                       all_h, all_c);

    // 4) convert all_h -> fp16
    hconv_kernel<<<(TT * BB * HH) / 256, 256>>>(all_h);

    // 5) tensor-core y-projection (fp16 1-pass mma.sync)
    dim3 yg(NPAD2 / 256, (TT * BB) / 128);   // 40 x 128
    ysync_kernel<<<yg, 512, YSM_TOTAL>>>(Woutb, all_y);
}

// round 15
// speedup vs baseline: 2.2172x; 1.1551x over previous
#include <cuda_runtime.h>
#include <cuda_bf16.h>
#include <cuda_fp16.h>
#include <cstdint>

// Problem constants
#define TT 256
#define BB 64
#define EE 512
#define HH 1024
#define VV 10000
#define G4 4096      // 4*H
#define NCTA 128
#define NTHR 512

// HMMA tiling
#define NPAD2 10240           // VV padded to multiple of 256 (40 tiles)
#define YST 30720             // bytes/stage: A 128x80 + B 256x80
#define YSM_TOTAL (4 * YST)   // 120 KB, 4-stage pipeline

// Scratch (no cudaMalloc allowed): device globals
__device__ float g_gx  [(size_t)TT * BB * G4];            // [T*B][4H] fp32  256 MB
__device__ unsigned g_bar_count;
__device__ unsigned g_bar_phase;
__device__ __half g_xh[(size_t)TT * BB * EE];             // fp16 x_emb      16.8 MB
__device__ __half g_wx[(size_t)G4 * EE];                  // fp16 W_x^T      4 MB
__device__ float  g_gbias[G4];                            // packed gate bias
__device__ __half g_ah[(size_t)TT * BB * HH];             // fp16(all_h)     33.5 MB
__device__ __half g_bh[(size_t)NPAD2 * HH];               // fp16(Wout^T)    21 MB

// ===========================================================================
// Helpers
// ===========================================================================
__device__ __forceinline__ uint32_t smem_to_u32(const void* p) {
    uint32_t a;
    asm("{ .reg .u64 t; cvta.to.shared.u64 t, %1; cvt.u32.u64 %0, t; }"
        : "=r"(a) : "l"(p));
    return a;
}
__device__ __forceinline__ void cp16(uint32_t dst, const void* src) {
    asm volatile("cp.async.cg.shared.global [%0], [%1], 16;\n"
                 :: "r"(dst), "l"(src) : "memory");
}
__device__ __forceinline__ void ldsm4(uint32_t& r0, uint32_t& r1,
                                      uint32_t& r2, uint32_t& r3, uint32_t a) {
    asm volatile("ldmatrix.sync.aligned.m8n8.x4.shared.b16 {%0,%1,%2,%3}, [%4];"
                 : "=r"(r0), "=r"(r1), "=r"(r2), "=r"(r3) : "r"(a));
}
__device__ __forceinline__ void hmma16(float* d, const uint32_t* a, const uint32_t* b) {
    asm volatile("mma.sync.aligned.m16n8k16.row.col.f32.f16.f16.f32 "
                 "{%0,%1,%2,%3}, {%4,%5,%6,%7}, {%8,%9}, {%0,%1,%2,%3};"
                 : "+f"(d[0]), "+f"(d[1]), "+f"(d[2]), "+f"(d[3])
                 : "r"(a[0]), "r"(a[1]), "r"(a[2]), "r"(a[3]),
                   "r"(b[0]), "r"(b[1]));
}

// ---------------------------------------------------------------------------
// Kernel 1: embedding gather -> fp16 directly
// ---------------------------------------------------------------------------
__global__ void embed_kernel(const int* __restrict__ x, const float* __restrict__ emb) {
    int row = blockIdx.x;                 // t*B + b
    int idx = x[row];
    const float4* src = (const float4*)(emb + (size_t)idx * EE);
    float4 v = src[threadIdx.x];
    __half2 h0 = __floats2half2_rn(v.x, v.y);
    __half2 h1 = __floats2half2_rn(v.z, v.w);
    uint2* dst = (uint2*)(g_xh + (size_t)row * EE);
    uint2 pk;
    pk.x = *(uint32_t*)&h0;
    pk.y = *(uint32_t*)&h1;
    dst[threadIdx.x] = pk;
}

// ---------------------------------------------------------------------------
// Kernel 2a: transpose + convert W_x (rows [H,H+E) of each gate) -> g_wx[4H][E]
// grid (EE/32, HH/32, 4), block (32,8)
// ---------------------------------------------------------------------------
__global__ void __launch_bounds__(256)
wgxconv_kernel(const float* __restrict__ Wf, const float* __restrict__ Wi,
               const float* __restrict__ Wc, const float* __restrict__ Wo) {
    __shared__ float t[32][33];
    const int gate = blockIdx.z;
    const float* W = (gate == 0) ? Wf : (gate == 1) ? Wi : (gate == 2) ? Wc : Wo;
    int k0 = blockIdx.x * 32, n0 = blockIdx.y * 32;
    int tx = threadIdx.x, ty = threadIdx.y;
#pragma unroll
    for (int j = 0; j < 4; ++j) {
        int k = k0 + ty + j * 8;          // k in [0,E)
        t[ty + j * 8][tx] = W[(size_t)(HH + k) * HH + n0 + tx];
    }
    __syncthreads();
#pragma unroll
    for (int j = 0; j < 4; ++j) {
        int n = n0 + ty + j * 8;          // column j within gate's H
        int k = k0 + tx;
        g_wx[(size_t)(gate * HH + n) * EE + k] = __float2half(t[tx][ty + j * 8]);
    }
}

// Kernel 2b: pack gate biases into g_gbias[4H]
__global__ void bias_pack_kernel(const float* __restrict__ bf, const float* __restrict__ bi,
                                 const float* __restrict__ bc, const float* __restrict__ bo) {
    int n = blockIdx.x * 256 + threadIdx.x;
    int gate = n >> 10, j = n & (HH - 1);
    const float* b = (gate == 0) ? bf : (gate == 1) ? bi : (gate == 2) ? bc : bo;
    g_gbias[n] = b[j];
}

// ---------------------------------------------------------------------------
// Kernel 2c: fp16 HMMA gx-GEMM  g_gx = x_emb @ W_x^T + bias
// M=16384, N=4096, K=512. 128x256 tile/CTA, 512 thr, 4-stage cp.async.
// Verbatim clone of the proven ysync pipeline with K=512.
// ---------------------------------------------------------------------------
__device__ __forceinline__ void gx_fill(uint32_t sb, int stage, int m0, int n0,
                                        int kb, int tid) {
    uint32_t tb = sb + stage * YST;
    {
        int row = tid >> 2;               // 0..127
        int ch  = tid & 3;
        cp16(tb + row * 80 + ch * 16,
             g_xh + (size_t)(m0 + row) * EE + kb + ch * 8);
    }
#pragma unroll
    for (int i = 0; i < 2; ++i) {
        int idx = tid + i * 512;          // 0..1023
        int row = idx >> 2;               // 0..255
        int ch  = idx & 3;
        cp16(tb + 10240 + row * 80 + ch * 16,
             g_wx + (size_t)(n0 + row) * EE + kb + ch * 8);
    }
    asm volatile("cp.async.commit_group;" ::: "memory");
}

__global__ void __launch_bounds__(512, 1)
gxsync_kernel() {
    extern __shared__ char ysm[];
    uint32_t sb = smem_to_u32(ysm);
    const int tid = threadIdx.x;
    const int lane = tid & 31;
    const int wid = tid >> 5;
    const int wm = wid & 1;
    const int wn = wid >> 1;
    const int n0 = blockIdx.x * 256;
    const int m0 = blockIdx.y * 128;

    const int lrow = lane & 7;
    const int sub  = lane >> 3;
    const int r16  = (sub & 1) * 8 + lrow;
    const int kby  = (sub >> 1) * 16;

    float acc[4][4][4];
#pragma unroll
    for (int a = 0; a < 4; ++a)
#pragma unroll
        for (int b = 0; b < 4; ++b)
#pragma unroll
            for (int d = 0; d < 4; ++d) acc[a][b][d] = 0.0f;

    gx_fill(sb, 0, m0, n0, 0,  tid);
    gx_fill(sb, 1, m0, n0, 32, tid);
    gx_fill(sb, 2, m0, n0, 64, tid);

#pragma unroll 1
    for (int it = 0; it < 16; ++it) {
        if (it < 14)       asm volatile("cp.async.wait_group 2;" ::: "memory");
        else if (it == 14) asm volatile("cp.async.wait_group 1;" ::: "memory");
        else               asm volatile("cp.async.wait_group 0;" ::: "memory");
        __syncthreads();

        uint32_t tb = sb + (it & 3) * YST;

#pragma unroll
        for (int ks = 0; ks < 2; ++ks) {
            uint32_t ah[4][4], bf2[4][2];
#pragma unroll
            for (int mf = 0; mf < 4; ++mf) {
                uint32_t ab = tb + (uint32_t)(wm * 64 + mf * 16 + r16) * 80
                            + ks * 32 + kby;
                ldsm4(ah[mf][0], ah[mf][1], ah[mf][2], ah[mf][3], ab);
            }
#pragma unroll
            for (int nf = 0; nf < 2; ++nf) {
                uint32_t bb = tb + 10240
                            + (uint32_t)(wn * 32 + nf * 16 + r16) * 80
                            + ks * 32 + kby;
                uint32_t r0, r1, r2, r3;
                ldsm4(r0, r1, r2, r3, bb);
                bf2[2 * nf][0] = r0;      bf2[2 * nf][1] = r2;
                bf2[2 * nf + 1][0] = r1;  bf2[2 * nf + 1][1] = r3;
            }
#pragma unroll
            for (int mf = 0; mf < 4; ++mf)
#pragma unroll
                for (int nb = 0; nb < 4; ++nb)
                    hmma16(acc[mf][nb], ah[mf], bf2[nb]);
        }

        if (it + 3 < 16) gx_fill(sb, (it + 3) & 3, m0, n0, (it + 3) * 32, tid);
    }

    const int g  = lane >> 2;
    const int i2 = (lane & 3) * 2;
#pragma unroll
    for (int mf = 0; mf < 4; ++mf) {
        int r0 = m0 + wm * 64 + mf * 16 + g;
#pragma unroll
        for (int nb = 0; nb < 4; ++nb) {
            int cc = n0 + wn * 32 + nb * 8 + i2;
            float b0 = g_gbias[cc], b1 = g_gbias[cc + 1];
            float2 v0 = make_float2(acc[mf][nb][0] + b0, acc[mf][nb][1] + b1);
            *(float2*)(g_gx + (size_t)r0 * G4 + cc) = v0;
            float2 v1 = make_float2(acc[mf][nb][2] + b0, acc[mf][nb][3] + b1);
            *(float2*)(g_gx + (size_t)(r0 + 8) * G4 + cc) = v1;
        }
    }
}

// ---------------------------------------------------------------------------
// Kernel 3: persistent LSTM recurrence (proven; + fp16 h write in epilogue)
// ---------------------------------------------------------------------------
#define SMEM_FLOATS (43524)
#define SMEM_BYTES  (SMEM_FLOATS * 4)

__device__ __forceinline__ float sigmoidf_(float x) {
    return 1.0f / (1.0f + __expf(-x));
}

__device__ __forceinline__ void slab_load_async(float* dst, const float* hsrc,
                                                int rb, int tid) {
#pragma unroll
    for (int q = 0; q < 8; ++q) {
        int idx = tid + q * NTHR;
        int row = idx >> 8;
        int c4  = idx & 255;
        const float* src = hsrc + (size_t)(rb * 16 + row) * HH + c4 * 4;
        unsigned dsta = (unsigned)__cvta_generic_to_shared(dst + row * HH + c4 * 4);
        asm volatile("cp.async.cg.shared.global [%0], [%1], 16;\n"
                     :: "r"(dsta), "l"(src) : "memory");
    }
}

__device__ __forceinline__ void grid_bar(unsigned target) {
    __syncthreads();
    if (threadIdx.x == 0) {
        __threadfence();
        unsigned old = atomicAdd(&g_bar_count, 1u);
        if (old == NCTA - 1) {
            atomicExch(&g_bar_count, 0u);
            __threadfence();
            atomicAdd(&g_bar_phase, 1u);
        } else {
            while ((int)(*((volatile unsigned*)&g_bar_phase) - target) < 0) {}
            __threadfence();
        }
    }
    __syncthreads();
}

__global__ void __launch_bounds__(NTHR, 1)
lstm_persistent_kernel(const float* __restrict__ h0, const float* __restrict__ c0,
                       const float* __restrict__ Wf, const float* __restrict__ Wi,
                       const float* __restrict__ Wc, const float* __restrict__ Wo,
                       float* __restrict__ all_h, float* __restrict__ all_c) {
    extern __shared__ float smem[];
    float* hs0 = smem;
    float* hs1 = smem + 16384;
    float* sc  = smem + 32768;
    float* gsm = smem + 43008;
    unsigned* shp = (unsigned*)(smem + 43520);

    const int tid = threadIdx.x;
    const int kg  = tid >> 5;
    const int c   = tid & 31;
    const int gate = c >> 3;
    const int jo   = c & 7;
    const int n    = blockIdx.x;
    const int j    = n * 8 + jo;

    const float* Wg = (gate == 0) ? Wf : (gate == 1) ? Wi : (gate == 2) ? Wc : Wo;

    float w[64];
#pragma unroll
    for (int kk = 0; kk < 64; ++kk)
        w[kk] = Wg[(size_t)(kg * 64 + kk) * HH + j];

    if (tid == 0) shp[0] = *((volatile unsigned*)&g_bar_phase);
    __syncthreads();
    const unsigned phase_base = shp[0];

    const int r_ml = tid >> 5;
    const int r_c  = tid & 31;
    const int r_cgl = (r_c >> 3) * HH + n * 8 + (r_c & 7);

    for (int t = 0; t < TT; ++t) {
        const float* hsrc = (t == 0) ? h0 : all_h + (size_t)(t - 1) * BB * HH;
        const float* csrc = (t == 0) ? c0 : all_c + (size_t)(t - 1) * BB * HH;
        float* hdst = all_h + (size_t)t * BB * HH;
        float* cdst = all_c + (size_t)t * BB * HH;

        slab_load_async(hs0, hsrc, 0, tid);
        asm volatile("cp.async.commit_group;\n" ::: "memory");
        asm volatile("cp.async.wait_group 0;\n" ::: "memory");
        __syncthreads();

#pragma unroll 1
        for (int rb = 0; rb < 4; ++rb) {
            float* cur = (rb & 1) ? hs1 : hs0;
            float* nxt = (rb & 1) ? hs0 : hs1;
            if (rb < 3) {
                slab_load_async(nxt, hsrc, rb + 1, tid);
                asm volatile("cp.async.commit_group;\n" ::: "memory");
            }

            const float* hbase = cur + kg * 64;
#pragma unroll 1
            for (int mi = 0; mi < 16; ++mi) {
                const float4* h4 = (const float4*)(hbase + mi * HH);
                float a0 = 0.f, a1 = 0.f, a2 = 0.f, a3 = 0.f;
#pragma unroll
                for (int q = 0; q < 16; ++q) {
                    float4 v = h4[q];
                    a0 = fmaf(v.x, w[4 * q + 0], a0);
                    a1 = fmaf(v.y, w[4 * q + 1], a1);
                    a2 = fmaf(v.z, w[4 * q + 2], a2);
                    a3 = fmaf(v.w, w[4 * q + 3], a3);
                }
                sc[(mi * 32 + c) * 20 + kg] = (a0 + a1) + (a2 + a3);
            }
            __syncthreads();

            {
                const float* p = sc + (r_ml * 32 + r_c) * 20;
                float4 s0 = *(const float4*)(p);
                float4 s1 = *(const float4*)(p + 4);
                float4 s2 = *(const float4*)(p + 8);
                float4 s3 = *(const float4*)(p + 12);
                float s = ((s0.x + s0.y) + (s0.z + s0.w))
                        + ((s1.x + s1.y) + (s1.z + s1.w))
                        + ((s2.x + s2.y) + (s2.z + s2.w))
                        + ((s3.x + s3.y) + (s3.z + s3.w));
                int mrow = rb * 16 + r_ml;
                s += g_gx[((size_t)t * BB + mrow) * G4 + r_cgl];
                gsm[r_ml * 32 + r_c] = s;
            }
            __syncthreads();

            if (tid < 128) {
                int ml = tid >> 3;
                int jj = tid & 7;
                int mrow = rb * 16 + ml;
                const float* g = gsm + ml * 32;
                float f  = sigmoidf_(g[jj]);
                float ii = sigmoidf_(g[8 + jj]);
                float cd = tanhf(g[16 + jj]);
                float o  = sigmoidf_(g[24 + jj]);
                size_t off = (size_t)mrow * HH + n * 8 + jj;
                float cn = f * csrc[off] + ii * cd;
                cdst[off] = cn;
                float hv = o * tanhf(cn);
                hdst[off] = hv;
                g_ah[(size_t)t * BB * HH + off] = __float2half(hv);   // fused hconv
            }
            if (rb < 3) asm volatile("cp.async.wait_group 0;\n" ::: "memory");
            __syncthreads();
        }

        grid_bar(phase_base + (unsigned)t + 1u);
    }
}

// ---------------------------------------------------------------------------
// Kernel 4: transpose + convert Wout [K][V] -> g_bh [NPAD2][K] fp16 (zero-pad)
// ---------------------------------------------------------------------------
__global__ void __launch_bounds__(256)
wconv_kernel(const float* __restrict__ W) {
    __shared__ float t[32][33];
    int k0 = blockIdx.x * 32, n0 = blockIdx.y * 32;
    int tx = threadIdx.x, ty = threadIdx.y;
#pragma unroll
    for (int j = 0; j < 4; ++j) {
        int k = k0 + ty + j * 8, n = n0 + tx;
        t[ty + j * 8][tx] = (n < VV) ? W[(size_t)k * VV + n] : 0.0f;
    }
    __syncthreads();
#pragma unroll
    for (int j = 0; j < 4; ++j) {
        int n = n0 + ty + j * 8, k = k0 + tx;
        g_bh[(size_t)n * HH + k] = __float2half(t[tx][ty + j * 8]);
    }
}

// ---------------------------------------------------------------------------
// Kernel 5: fp16 1-pass mma.sync y-GEMM  Y = A@B^T + bias  (proven R14)
// ---------------------------------------------------------------------------
__device__ __forceinline__ void y_fill(uint32_t sb, int stage, int m0, int n0,
                                       int kb, int tid) {
    uint32_t tb = sb + stage * YST;
    {
        int row = tid >> 2;
        int ch  = tid & 3;
        cp16(tb + row * 80 + ch * 16,
             g_ah + (size_t)(m0 + row) * HH + kb + ch * 8);
    }
#pragma unroll
    for (int i = 0; i < 2; ++i) {
        int idx = tid + i * 512;
        int row = idx >> 2;
        int ch  = idx & 3;
        cp16(tb + 10240 + row * 80 + ch * 16,
             g_bh + (size_t)(n0 + row) * HH + kb + ch * 8);
    }
    asm volatile("cp.async.commit_group;" ::: "memory");
}

__global__ void __launch_bounds__(512, 1)
ysync_kernel(const float* __restrict__ bout, float* __restrict__ Y) {
    extern __shared__ char ysm[];
    uint32_t sb = smem_to_u32(ysm);
    const int tid = threadIdx.x;
    const int lane = tid & 31;
    const int wid = tid >> 5;
    const int wm = wid & 1;
    const int wn = wid >> 1;
    const int n0 = blockIdx.x * 256;
    const int m0 = blockIdx.y * 128;

    const int lrow = lane & 7;
    const int sub  = lane >> 3;
    const int r16  = (sub & 1) * 8 + lrow;
    const int kby  = (sub >> 1) * 16;

    float acc[4][4][4];
#pragma unroll
    for (int a = 0; a < 4; ++a)
#pragma unroll
        for (int b = 0; b < 4; ++b)
#pragma unroll
            for (int d = 0; d < 4; ++d) acc[a][b][d] = 0.0f;

    y_fill(sb, 0, m0, n0, 0,  tid);
    y_fill(sb, 1, m0, n0, 32, tid);
    y_fill(sb, 2, m0, n0, 64, tid);

#pragma unroll 1
    for (int it = 0; it < 32; ++it) {
        if (it < 30)       asm volatile("cp.async.wait_group 2;" ::: "memory");
        else if (it == 30) asm volatile("cp.async.wait_group 1;" ::: "memory");
        else               asm volatile("cp.async.wait_group 0;" ::: "memory");
        __syncthreads();

        uint32_t tb = sb + (it & 3) * YST;

#pragma unroll
        for (int ks = 0; ks < 2; ++ks) {
            uint32_t ah[4][4], bf2[4][2];
#pragma unroll
            for (int mf = 0; mf < 4; ++mf) {
                uint32_t ab = tb + (uint32_t)(wm * 64 + mf * 16 + r16) * 80
                            + ks * 32 + kby;
                ldsm4(ah[mf][0], ah[mf][1], ah[mf][2], ah[mf][3], ab);
            }
#pragma unroll
            for (int nf = 0; nf < 2; ++nf) {
                uint32_t bb = tb + 10240
                            + (uint32_t)(wn * 32 + nf * 16 + r16) * 80
                            + ks * 32 + kby;
                uint32_t r0, r1, r2, r3;
                ldsm4(r0, r1, r2, r3, bb);
                bf2[2 * nf][0] = r0;      bf2[2 * nf][1] = r2;
                bf2[2 * nf + 1][0] = r1;  bf2[2 * nf + 1][1] = r3;
            }
#pragma unroll
            for (int mf = 0; mf < 4; ++mf)
#pragma unroll
                for (int nb = 0; nb < 4; ++nb)
                    hmma16(acc[mf][nb], ah[mf], bf2[nb]);
        }

        if (it + 3 < 32) y_fill(sb, (it + 3) & 3, m0, n0, (it + 3) * 32, tid);
    }

    const int g  = lane >> 2;
    const int i2 = (lane & 3) * 2;
#pragma unroll
    for (int mf = 0; mf < 4; ++mf) {
        int r0 = m0 + wm * 64 + mf * 16 + g;
#pragma unroll
        for (int nb = 0; nb < 4; ++nb) {
            int cc = n0 + wn * 32 + nb * 8 + i2;
            if (cc < VV) {
                float b0 = bout[cc], b1 = bout[cc + 1];
                float2 v0 = make_float2(acc[mf][nb][0] + b0, acc[mf][nb][1] + b1);
                *(float2*)(Y + (size_t)r0 * VV + cc) = v0;
                float2 v1 = make_float2(acc[mf][nb][2] + b0, acc[mf][nb][3] + b1);
                *(float2*)(Y + (size_t)(r0 + 8) * VV + cc) = v1;
            }
        }
    }
}

// ---------------------------------------------------------------------------
// Launch
// ---------------------------------------------------------------------------
extern "C" void kernel_launch(void* const* d_in, const int* in_sizes, int n_in,
                              void* d_out, int out_size) {
    const int*   x     = (const int*)d_in[0];
    const float* h0    = (const float*)d_in[1];
    const float* c0    = (const float*)d_in[2];
    const float* emb   = (const float*)d_in[3];
    const float* Wf_w  = (const float*)d_in[4];
    const float* Wf_b  = (const float*)d_in[5];
    const float* Wi_w  = (const float*)d_in[6];
    const float* Wi_b  = (const float*)d_in[7];
    const float* Wc_w  = (const float*)d_in[8];
    const float* Wc_b  = (const float*)d_in[9];
    const float* Wo_w  = (const float*)d_in[10];
    const float* Wo_b  = (const float*)d_in[11];
    const float* Woutw = (const float*)d_in[12];
    const float* Woutb = (const float*)d_in[13];

    float* out   = (float*)d_out;
    float* all_h = out;
    float* all_c = out + (size_t)TT * BB * HH;
    float* all_y = out + (size_t)2 * TT * BB * HH;

    cudaFuncSetAttribute(lstm_persistent_kernel,
                         cudaFuncAttributeMaxDynamicSharedMemorySize, SMEM_BYTES);
    cudaFuncSetAttribute(ysync_kernel,
                         cudaFuncAttributeMaxDynamicSharedMemorySize, YSM_TOTAL);
    cudaFuncSetAttribute(gxsync_kernel,
                         cudaFuncAttributeMaxDynamicSharedMemorySize, YSM_TOTAL);

    // 1) gather embeddings -> fp16
    embed_kernel<<<TT * BB, 128>>>(x, emb);

    // 2) prep: W_x transpose->fp16, packed bias, Wout transpose->fp16
    dim3 wxg(EE / 32, HH / 32, 4);
    wgxconv_kernel<<<wxg, dim3(32, 8)>>>(Wf_w, Wi_w, Wc_w, Wo_w);
    bias_pack_kernel<<<G4 / 256, 256>>>(Wf_b, Wi_b, Wc_b, Wo_b);
    dim3 wsg(HH / 32, NPAD2 / 32);
    wconv_kernel<<<wsg, dim3(32, 8)>>>(Woutw);

    // 3) gx = x_emb @ W_x^T + bias  (fp16 HMMA)
    dim3 gxg(G4 / 256, (TT * BB) / 128);   // 16 x 128
    gxsync_kernel<<<gxg, 512, YSM_TOTAL>>>();

    // 4) recurrence (persistent, fp32; writes fp16 h copy)
    lstm_persistent_kernel<<<NCTA, NTHR, SMEM_BYTES>>>(h0, c0,
                                                       Wf_w, Wi_w, Wc_w, Wo_w,
                                                       all_h, all_c);

    // 5) tensor-core y-projection (fp16 1-pass mma.sync)
    dim3 yg(NPAD2 / 256, (TT * BB) / 128);   // 40 x 128
    ysync_kernel<<<yg, 512, YSM_TOTAL>>>(Woutb, all_y);
}

// round 16
// speedup vs baseline: 4.9957x; 2.2531x over previous
#include <cuda_runtime.h>
#include <cuda_bf16.h>
#include <cuda_fp16.h>
#include <cstdint>

// Problem constants
#define TT 256
#define BB 64
#define EE 512
#define HH 1024
#define VV 10000
#define G4 4096      // 4*H
#define NCTA 128
#define NTHR 512

// HMMA tiling (gx / y GEMMs)
#define NPAD2 10240           // VV padded to multiple of 256 (40 tiles)
#define YST 30720             // bytes/stage: A 128x80 + B 256x80
#define YSM_TOTAL (4 * YST)   // 120 KB, 4-stage pipeline

// Persistent-recurrence smem layout (bytes), row stride 2064 (16 mod 128 -> conflict-free ldmatrix)
#define RST 2064
#define R_HSM   0                       // h slab: 64 rows x 2048B (+pad)
#define R_WSM   (64 * RST)              // W tile: 32 rows x 2048B (+pad)  @132096
#define R_GSM   (R_WSM + 32 * RST)      // fp32 partials [2][64][32]       @198144
#define R_SHP   (R_GSM + 2 * 64 * 32 * 4)
#define RSM_TOTAL (R_SHP + 16)          // ~214.6 KB

// Scratch (no cudaMalloc allowed): device globals
__device__ float g_gx  [(size_t)TT * BB * G4];            // [T*B][4H] fp32  256 MB
__device__ unsigned g_bar_count;
__device__ unsigned g_bar_phase;
__device__ __half g_xh[(size_t)TT * BB * EE];             // fp16 x_emb      16.8 MB
__device__ __half g_wx[(size_t)G4 * EE];                  // fp16 W_x^T      4 MB
__device__ float  g_gbias[G4];                            // packed gate bias
__device__ __half g_ah[(size_t)TT * BB * HH];             // fp16(all_h)     33.5 MB
__device__ __half g_h0h[(size_t)BB * HH];                 // fp16(h0)
__device__ __half g_wh[(size_t)G4 * HH];                  // fp16 packed W_h^T  8 MB
__device__ __half g_bh[(size_t)NPAD2 * HH];               // fp16(Wout^T)    21 MB

// ===========================================================================
// Helpers
// ===========================================================================
__device__ __forceinline__ uint32_t smem_to_u32(const void* p) {
    uint32_t a;
    asm("{ .reg .u64 t; cvta.to.shared.u64 t, %1; cvt.u32.u64 %0, t; }"
        : "=r"(a) : "l"(p));
    return a;
}
__device__ __forceinline__ void cp16(uint32_t dst, const void* src) {
    asm volatile("cp.async.cg.shared.global [%0], [%1], 16;\n"
                 :: "r"(dst), "l"(src) : "memory");
}
__device__ __forceinline__ void ldsm4(uint32_t& r0, uint32_t& r1,
                                      uint32_t& r2, uint32_t& r3, uint32_t a) {
    asm volatile("ldmatrix.sync.aligned.m8n8.x4.shared.b16 {%0,%1,%2,%3}, [%4];"
                 : "=r"(r0), "=r"(r1), "=r"(r2), "=r"(r3) : "r"(a));
}
__device__ __forceinline__ void hmma16(float* d, const uint32_t* a, const uint32_t* b) {
    asm volatile("mma.sync.aligned.m16n8k16.row.col.f32.f16.f16.f32 "
                 "{%0,%1,%2,%3}, {%4,%5,%6,%7}, {%8,%9}, {%0,%1,%2,%3};"
                 : "+f"(d[0]), "+f"(d[1]), "+f"(d[2]), "+f"(d[3])
                 : "r"(a[0]), "r"(a[1]), "r"(a[2]), "r"(a[3]),
                   "r"(b[0]), "r"(b[1]));
}
__device__ __forceinline__ float sigmoidf_(float x) {
    return 1.0f / (1.0f + __expf(-x));
}

// ---------------------------------------------------------------------------
// Kernel 1: embedding gather -> fp16 directly
// ---------------------------------------------------------------------------
__global__ void embed_kernel(const int* __restrict__ x, const float* __restrict__ emb) {
    int row = blockIdx.x;
    int idx = x[row];
    const float4* src = (const float4*)(emb + (size_t)idx * EE);
    float4 v = src[threadIdx.x];
    __half2 h0 = __floats2half2_rn(v.x, v.y);
    __half2 h1 = __floats2half2_rn(v.z, v.w);
    uint2* dst = (uint2*)(g_xh + (size_t)row * EE);
    uint2 pk;
    pk.x = *(uint32_t*)&h0;
    pk.y = *(uint32_t*)&h1;
    dst[threadIdx.x] = pk;
}

// ---------------------------------------------------------------------------
// Kernel 2a: transpose + convert W_x (rows [H,H+E)) -> g_wx[4H][E] fp16
// ---------------------------------------------------------------------------
__global__ void __launch_bounds__(256)
wgxconv_kernel(const float* __restrict__ Wf, const float* __restrict__ Wi,
               const float* __restrict__ Wc, const float* __restrict__ Wo) {
    __shared__ float t[32][33];
    const int gate = blockIdx.z;
    const float* W = (gate == 0) ? Wf : (gate == 1) ? Wi : (gate == 2) ? Wc : Wo;
    int k0 = blockIdx.x * 32, n0 = blockIdx.y * 32;
    int tx = threadIdx.x, ty = threadIdx.y;
#pragma unroll
    for (int j = 0; j < 4; ++j) {
        int k = k0 + ty + j * 8;
        t[ty + j * 8][tx] = W[(size_t)(HH + k) * HH + n0 + tx];
    }
    __syncthreads();
#pragma unroll
    for (int j = 0; j < 4; ++j) {
        int n = n0 + ty + j * 8;
        int k = k0 + tx;
        g_wx[(size_t)(gate * HH + n) * EE + k] = __float2half(t[tx][ty + j * 8]);
    }
}

// Kernel 2b: transpose + convert W_h (rows [0,H)) -> g_wh packed fp16
// packed row p = (j>>3)*32 + gate*8 + (j&7)  (CTA n owns rows [n*32, n*32+32))
__global__ void __launch_bounds__(256)
whconv_kernel(const float* __restrict__ Wf, const float* __restrict__ Wi,
              const float* __restrict__ Wc, const float* __restrict__ Wo) {
    __shared__ float t[32][33];
    const int gate = blockIdx.z;
    const float* W = (gate == 0) ? Wf : (gate == 1) ? Wi : (gate == 2) ? Wc : Wo;
    int k0 = blockIdx.x * 32, j0 = blockIdx.y * 32;
    int tx = threadIdx.x, ty = threadIdx.y;
#pragma unroll
    for (int jj = 0; jj < 4; ++jj) {
        int k = k0 + ty + jj * 8;
        t[ty + jj * 8][tx] = W[(size_t)k * HH + j0 + tx];
    }
    __syncthreads();
#pragma unroll
    for (int jj = 0; jj < 4; ++jj) {
        int j = j0 + ty + jj * 8;
        int k = k0 + tx;
        int p = ((j >> 3) << 5) + gate * 8 + (j & 7);
        g_wh[(size_t)p * HH + k] = __float2half(t[tx][ty + jj * 8]);
    }
}

// Kernel 2c: pack gate biases
__global__ void bias_pack_kernel(const float* __restrict__ bf, const float* __restrict__ bi,
                                 const float* __restrict__ bc, const float* __restrict__ bo) {
    int n = blockIdx.x * 256 + threadIdx.x;
    int gate = n >> 10, j = n & (HH - 1);
    const float* b = (gate == 0) ? bf : (gate == 1) ? bi : (gate == 2) ? bc : bo;
    g_gbias[n] = b[j];
}

// Kernel 2d: h0 -> fp16
__global__ void h0conv_kernel(const float* __restrict__ h0) {
    int i = blockIdx.x * 256 + threadIdx.x;
    g_h0h[i] = __float2half(h0[i]);
}

// ---------------------------------------------------------------------------
// Kernel 3: fp16 HMMA gx-GEMM  g_gx = x_emb @ W_x^T + bias  (proven R15)
// ---------------------------------------------------------------------------
__device__ __forceinline__ void gx_fill(uint32_t sb, int stage, int m0, int n0,
                                        int kb, int tid) {
    uint32_t tb = sb + stage * YST;
    {
        int row = tid >> 2;
        int ch  = tid & 3;
        cp16(tb + row * 80 + ch * 16,
             g_xh + (size_t)(m0 + row) * EE + kb + ch * 8);
    }
#pragma unroll
    for (int i = 0; i < 2; ++i) {
        int idx = tid + i * 512;
        int row = idx >> 2;
        int ch  = idx & 3;
        cp16(tb + 10240 + row * 80 + ch * 16,
             g_wx + (size_t)(n0 + row) * EE + kb + ch * 8);
    }
    asm volatile("cp.async.commit_group;" ::: "memory");
}

__global__ void __launch_bounds__(512, 1)
gxsync_kernel() {
    extern __shared__ char ysm[];
    uint32_t sb = smem_to_u32(ysm);
    const int tid = threadIdx.x;
    const int lane = tid & 31;
    const int wid = tid >> 5;
    const int wm = wid & 1;
    const int wn = wid >> 1;
    const int n0 = blockIdx.x * 256;
    const int m0 = blockIdx.y * 128;

    const int lrow = lane & 7;
    const int sub  = lane >> 3;
    const int r16  = (sub & 1) * 8 + lrow;
    const int kby  = (sub >> 1) * 16;

    float acc[4][4][4];
#pragma unroll
    for (int a = 0; a < 4; ++a)
#pragma unroll
        for (int b = 0; b < 4; ++b)
#pragma unroll
            for (int d = 0; d < 4; ++d) acc[a][b][d] = 0.0f;

    gx_fill(sb, 0, m0, n0, 0,  tid);
    gx_fill(sb, 1, m0, n0, 32, tid);
    gx_fill(sb, 2, m0, n0, 64, tid);

#pragma unroll 1
    for (int it = 0; it < 16; ++it) {
        if (it < 14)       asm volatile("cp.async.wait_group 2;" ::: "memory");
        else if (it == 14) asm volatile("cp.async.wait_group 1;" ::: "memory");
        else               asm volatile("cp.async.wait_group 0;" ::: "memory");
        __syncthreads();

        uint32_t tb = sb + (it & 3) * YST;

#pragma unroll
        for (int ks = 0; ks < 2; ++ks) {
            uint32_t ah[4][4], bf2[4][2];
#pragma unroll
            for (int mf = 0; mf < 4; ++mf) {
                uint32_t ab = tb + (uint32_t)(wm * 64 + mf * 16 + r16) * 80
                            + ks * 32 + kby;
                ldsm4(ah[mf][0], ah[mf][1], ah[mf][2], ah[mf][3], ab);
            }
#pragma unroll
            for (int nf = 0; nf < 2; ++nf) {
                uint32_t bb = tb + 10240
                            + (uint32_t)(wn * 32 + nf * 16 + r16) * 80
                            + ks * 32 + kby;
                uint32_t r0, r1, r2, r3;
                ldsm4(r0, r1, r2, r3, bb);
                bf2[2 * nf][0] = r0;      bf2[2 * nf][1] = r2;
                bf2[2 * nf + 1][0] = r1;  bf2[2 * nf + 1][1] = r3;
            }
#pragma unroll
            for (int mf = 0; mf < 4; ++mf)
#pragma unroll
                for (int nb = 0; nb < 4; ++nb)
                    hmma16(acc[mf][nb], ah[mf], bf2[nb]);
        }

        if (it + 3 < 16) gx_fill(sb, (it + 3) & 3, m0, n0, (it + 3) * 32, tid);
    }

    const int g  = lane >> 2;
    const int i2 = (lane & 3) * 2;
#pragma unroll
    for (int mf = 0; mf < 4; ++mf) {
        int r0 = m0 + wm * 64 + mf * 16 + g;
#pragma unroll
        for (int nb = 0; nb < 4; ++nb) {
            int cc = n0 + wn * 32 + nb * 8 + i2;
            float b0 = g_gbias[cc], b1 = g_gbias[cc + 1];
            float2 v0 = make_float2(acc[mf][nb][0] + b0, acc[mf][nb][1] + b1);
            *(float2*)(g_gx + (size_t)r0 * G4 + cc) = v0;
            float2 v1 = make_float2(acc[mf][nb][2] + b0, acc[mf][nb][3] + b1);
            *(float2*)(g_gx + (size_t)(r0 + 8) * G4 + cc) = v1;
        }
    }
}

// ---------------------------------------------------------------------------
// Kernel 4: persistent LSTM recurrence — fp16 HMMA mainloop, register c-state
// CTA n owns packed W rows [n*32, n*32+32) = H-cols [n*8,n*8+8) x 4 gates.
// 16 warps = (mw 0..3) x (nw16 0..1) x (ks 0..1): 16x16 tile, K-half 512.
// ---------------------------------------------------------------------------
__device__ __forceinline__ void grid_bar(unsigned target) {
    __syncthreads();
    if (threadIdx.x == 0) {
        __threadfence();
        unsigned old = atomicAdd(&g_bar_count, 1u);
        if (old == NCTA - 1) {
            atomicExch(&g_bar_count, 0u);
            __threadfence();
            atomicAdd(&g_bar_phase, 1u);
        } else {
            while ((int)(*((volatile unsigned*)&g_bar_phase) - target) < 0) {}
            __threadfence();
        }
    }
    __syncthreads();
}

__global__ void __launch_bounds__(NTHR, 1)
lstm_persistent_kernel(const float* __restrict__ c0,
                       float* __restrict__ all_h, float* __restrict__ all_c) {
    extern __shared__ char rsm[];
    uint32_t sb = smem_to_u32(rsm);
    const uint32_t hsm = sb + R_HSM;
    const uint32_t wsm = sb + R_WSM;
    float* gsm = (float*)(rsm + R_GSM);          // [2][64][32]
    unsigned* shp = (unsigned*)(rsm + R_SHP);

    const int tid = threadIdx.x;
    const int lane = tid & 31;
    const int wid = tid >> 5;
    const int mw   = wid & 3;          // m-tile (16 rows)
    const int nw16 = (wid >> 2) & 1;   // n-tile (16 packed cols)
    const int ksw  = wid >> 3;         // K-half
    const int n    = blockIdx.x;       // CTA: H-cols [n*8, n*8+8)

    const int lrow = lane & 7;
    const int sub  = lane >> 3;
    const int r16  = (sub & 1) * 8 + lrow;
    const int kby  = (sub >> 1) * 16;

    // ---- load W tile once (32 rows x 2048B)
#pragma unroll
    for (int q = 0; q < 8; ++q) {
        int idx = tid + q * NTHR;             // 0..4095
        int row = idx >> 7;                   // 0..31
        int ch  = idx & 127;
        cp16(wsm + row * RST + ch * 16,
             g_wh + (size_t)(n * 32 + row) * HH + ch * 8);
    }
    asm volatile("cp.async.commit_group;\n" ::: "memory");

    // ---- cell-thread state: thread (m = tid>>3, jo = tid&7)
    const int cm = tid >> 3;
    const int cj = tid & 7;
    const size_t coff = (size_t)cm * HH + n * 8 + cj;       // within [B][H]
    float c_reg = c0[coff];

    if (tid == 0) shp[0] = *((volatile unsigned*)&g_bar_phase);
    asm volatile("cp.async.wait_group 0;\n" ::: "memory");
    __syncthreads();
    const unsigned phase_base = shp[0];

    for (int t = 0; t < TT; ++t) {
        const __half* hsrc = (t == 0) ? g_h0h : g_ah + (size_t)(t - 1) * BB * HH;

        // ---- fill h slab (64 rows x 2048B fp16)
#pragma unroll
        for (int q = 0; q < 16; ++q) {
            int idx = tid + q * NTHR;         // 0..8191
            int row = idx >> 7;               // 0..63
            int ch  = idx & 127;
            cp16(hsm + row * RST + ch * 16,
                 hsrc + (size_t)row * HH + ch * 8);
        }
        asm volatile("cp.async.commit_group;\n" ::: "memory");
        asm volatile("cp.async.wait_group 0;\n" ::: "memory");
        __syncthreads();

        // ---- mma: 16x16 tile per warp over K-half 512
        float acc[2][4];
#pragma unroll
        for (int a = 0; a < 2; ++a)
#pragma unroll
            for (int d = 0; d < 4; ++d) acc[a][d] = 0.0f;

        const uint32_t abase = hsm + (uint32_t)(mw * 16 + r16) * RST + ksw * 1024 + kby;
        const uint32_t bbase = wsm + (uint32_t)(nw16 * 16 + r16) * RST + ksw * 1024 + kby;
#pragma unroll 4
        for (int ki = 0; ki < 32; ++ki) {
            uint32_t a0, a1, a2, a3, r0, r1, r2, r3;
            ldsm4(a0, a1, a2, a3, abase + ki * 32);
            ldsm4(r0, r1, r2, r3, bbase + ki * 32);
            uint32_t af[4] = {a0, a1, a2, a3};
            uint32_t b0[2] = {r0, r2};
            uint32_t b1[2] = {r1, r3};
            hmma16(acc[0], af, b0);
            hmma16(acc[1], af, b1);
        }

        // ---- write partials to gsm[ks][m][packed col]
        {
            int row = lane >> 2;
            int col = (lane & 3) * 2;
            float* base = gsm + ksw * 2048 + (mw * 16 + row) * 32 + nw16 * 16 + col;
            base[0] = acc[0][0];          base[1] = acc[0][1];
            base[8 * 32] = acc[0][2];     base[8 * 32 + 1] = acc[0][3];
            base[8] = acc[1][0];          base[9] = acc[1][1];
            base[8 * 32 + 8] = acc[1][2]; base[8 * 32 + 9] = acc[1][3];
        }
        __syncthreads();

        // ---- cell (all 512 threads, one (m, jo) each; c in register)
        {
            const float* gx = g_gx + ((size_t)t * BB + cm) * G4;
            const float* g0 = gsm + cm * 32;
            const float* g1 = gsm + 2048 + cm * 32;
            float gf = g0[cj]      + g1[cj]      + gx[n * 8 + cj];
            float gi = g0[8 + cj]  + g1[8 + cj]  + gx[HH + n * 8 + cj];
            float gc = g0[16 + cj] + g1[16 + cj] + gx[2 * HH + n * 8 + cj];
            float go = g0[24 + cj] + g1[24 + cj] + gx[3 * HH + n * 8 + cj];
            float f  = sigmoidf_(gf);
            float ii = sigmoidf_(gi);
            float cd = tanhf(gc);
            float o  = sigmoidf_(go);
            c_reg = f * c_reg + ii * cd;
            size_t off = (size_t)t * BB * HH + coff;
            all_c[off] = c_reg;
            float hv = o * tanhf(c_reg);
            all_h[off] = hv;
            g_ah[off] = __float2half(hv);
        }

        grid_bar(phase_base + (unsigned)t + 1u);
    }
}

// ---------------------------------------------------------------------------
// Kernel 5: transpose + convert Wout [K][V] -> g_bh [NPAD2][K] fp16 (zero-pad)
// ---------------------------------------------------------------------------
__global__ void __launch_bounds__(256)
wconv_kernel(const float* __restrict__ W) {
    __shared__ float t[32][33];
    int k0 = blockIdx.x * 32, n0 = blockIdx.y * 32;
    int tx = threadIdx.x, ty = threadIdx.y;
#pragma unroll
    for (int j = 0; j < 4; ++j) {
        int k = k0 + ty + j * 8, n = n0 + tx;
        t[ty + j * 8][tx] = (n < VV) ? W[(size_t)k * VV + n] : 0.0f;
    }
    __syncthreads();
#pragma unroll
    for (int j = 0; j < 4; ++j) {
        int n = n0 + ty + j * 8, k = k0 + tx;
        g_bh[(size_t)n * HH + k] = __float2half(t[tx][ty + j * 8]);
    }
}

// ---------------------------------------------------------------------------
// Kernel 6: fp16 1-pass mma.sync y-GEMM  Y = A@B^T + bias  (proven R14/R15)
// ---------------------------------------------------------------------------
__device__ __forceinline__ void y_fill(uint32_t sb, int stage, int m0, int n0,
                                       int kb, int tid) {
    uint32_t tb = sb + stage * YST;
    {
        int row = tid >> 2;
        int ch  = tid & 3;
        cp16(tb + row * 80 + ch * 16,
             g_ah + (size_t)(m0 + row) * HH + kb + ch * 8);
    }
#pragma unroll
    for (int i = 0; i < 2; ++i) {
        int idx = tid + i * 512;
        int row = idx >> 2;
        int ch  = idx & 3;
        cp16(tb + 10240 + row * 80 + ch * 16,
             g_bh + (size_t)(n0 + row) * HH + kb + ch * 8);
    }
    asm volatile("cp.async.commit_group;" ::: "memory");
}

__global__ void __launch_bounds__(512, 1)
ysync_kernel(const float* __restrict__ bout, float* __restrict__ Y) {
    extern __shared__ char ysm[];
    uint32_t sb = smem_to_u32(ysm);
    const int tid = threadIdx.x;
    const int lane = tid & 31;
    const int wid = tid >> 5;
    const int wm = wid & 1;
    const int wn = wid >> 1;
    const int n0 = blockIdx.x * 256;
    const int m0 = blockIdx.y * 128;

    const int lrow = lane & 7;
    const int sub  = lane >> 3;
    const int r16  = (sub & 1) * 8 + lrow;
    const int kby  = (sub >> 1) * 16;

    float acc[4][4][4];
#pragma unroll
    for (int a = 0; a < 4; ++a)
#pragma unroll
        for (int b = 0; b < 4; ++b)
#pragma unroll
            for (int d = 0; d < 4; ++d) acc[a][b][d] = 0.0f;

    y_fill(sb, 0, m0, n0, 0,  tid);
    y_fill(sb, 1, m0, n0, 32, tid);
    y_fill(sb, 2, m0, n0, 64, tid);

#pragma unroll 1
    for (int it = 0; it < 32; ++it) {
        if (it < 30)       asm volatile("cp.async.wait_group 2;" ::: "memory");
        else if (it == 30) asm volatile("cp.async.wait_group 1;" ::: "memory");
        else               asm volatile("cp.async.wait_group 0;" ::: "memory");
        __syncthreads();

        uint32_t tb = sb + (it & 3) * YST;

#pragma unroll
        for (int ks = 0; ks < 2; ++ks) {
            uint32_t ah[4][4], bf2[4][2];
#pragma unroll
            for (int mf = 0; mf < 4; ++mf) {
                uint32_t ab = tb + (uint32_t)(wm * 64 + mf * 16 + r16) * 80
                            + ks * 32 + kby;
                ldsm4(ah[mf][0], ah[mf][1], ah[mf][2], ah[mf][3], ab);
            }
#pragma unroll
            for (int nf = 0; nf < 2; ++nf) {
                uint32_t bb = tb + 10240
                            + (uint32_t)(wn * 32 + nf * 16 + r16) * 80
                            + ks * 32 + kby;
                uint32_t r0, r1, r2, r3;
                ldsm4(r0, r1, r2, r3, bb);
                bf2[2 * nf][0] = r0;      bf2[2 * nf][1] = r2;
                bf2[2 * nf + 1][0] = r1;  bf2[2 * nf + 1][1] = r3;
            }
#pragma unroll
            for (int mf = 0; mf < 4; ++mf)
#pragma unroll
                for (int nb = 0; nb < 4; ++nb)
                    hmma16(acc[mf][nb], ah[mf], bf2[nb]);
        }

        if (it + 3 < 32) y_fill(sb, (it + 3) & 3, m0, n0, (it + 3) * 32, tid);
    }

    const int g  = lane >> 2;
    const int i2 = (lane & 3) * 2;
#pragma unroll
    for (int mf = 0; mf < 4; ++mf) {
        int r0 = m0 + wm * 64 + mf * 16 + g;
#pragma unroll
        for (int nb = 0; nb < 4; ++nb) {
            int cc = n0 + wn * 32 + nb * 8 + i2;
            if (cc < VV) {
                float b0 = bout[cc], b1 = bout[cc + 1];
                float2 v0 = make_float2(acc[mf][nb][0] + b0, acc[mf][nb][1] + b1);
                *(float2*)(Y + (size_t)r0 * VV + cc) = v0;
                float2 v1 = make_float2(acc[mf][nb][2] + b0, acc[mf][nb][3] + b1);
                *(float2*)(Y + (size_t)(r0 + 8) * VV + cc) = v1;
            }
        }
    }
}

// ---------------------------------------------------------------------------
// Launch
// ---------------------------------------------------------------------------
extern "C" void kernel_launch(void* const* d_in, const int* in_sizes, int n_in,
                              void* d_out, int out_size) {
    const int*   x     = (const int*)d_in[0];
    const float* h0    = (const float*)d_in[1];
    const float* c0    = (const float*)d_in[2];
    const float* emb   = (const float*)d_in[3];
    const float* Wf_w  = (const float*)d_in[4];
    const float* Wf_b  = (const float*)d_in[5];
    const float* Wi_w  = (const float*)d_in[6];
    const float* Wi_b  = (const float*)d_in[7];
    const float* Wc_w  = (const float*)d_in[8];
    const float* Wc_b  = (const float*)d_in[9];
    const float* Wo_w  = (const float*)d_in[10];
    const float* Wo_b  = (const float*)d_in[11];
    const float* Woutw = (const float*)d_in[12];
    const float* Woutb = (const float*)d_in[13];

    float* out   = (float*)d_out;
    float* all_h = out;
    float* all_c = out + (size_t)TT * BB * HH;
    float* all_y = out + (size_t)2 * TT * BB * HH;

    cudaFuncSetAttribute(lstm_persistent_kernel,
                         cudaFuncAttributeMaxDynamicSharedMemorySize, RSM_TOTAL);
    cudaFuncSetAttribute(ysync_kernel,
                         cudaFuncAttributeMaxDynamicSharedMemorySize, YSM_TOTAL);
    cudaFuncSetAttribute(gxsync_kernel,
                         cudaFuncAttributeMaxDynamicSharedMemorySize, YSM_TOTAL);

    // 1) gather embeddings -> fp16
    embed_kernel<<<TT * BB, 128>>>(x, emb);

    // 2) prep: weight transposes/conversions, bias pack, h0 conversion
    dim3 wxg(EE / 32, HH / 32, 4);
    wgxconv_kernel<<<wxg, dim3(32, 8)>>>(Wf_w, Wi_w, Wc_w, Wo_w);
    dim3 whg(HH / 32, HH / 32, 4);
    whconv_kernel<<<whg, dim3(32, 8)>>>(Wf_w, Wi_w, Wc_w, Wo_w);
    bias_pack_kernel<<<G4 / 256, 256>>>(Wf_b, Wi_b, Wc_b, Wo_b);
    h0conv_kernel<<<(BB * HH) / 256, 256>>>(h0);
    dim3 wsg(HH / 32, NPAD2 / 32);
    wconv_kernel<<<wsg, dim3(32, 8)>>>(Woutw);

    // 3) gx = x_emb @ W_x^T + bias  (fp16 HMMA)
    dim3 gxg(G4 / 256, (TT * BB) / 128);   // 16 x 128
    gxsync_kernel<<<gxg, 512, YSM_TOTAL>>>();

    // 4) recurrence (persistent, fp16 HMMA mainloop, register c-state)
    lstm_persistent_kernel<<<NCTA, NTHR, RSM_TOTAL>>>(c0, all_h, all_c);

    // 5) tensor-core y-projection (fp16 1-pass mma.sync)
    dim3 yg(NPAD2 / 256, (TT * BB) / 128);   // 40 x 128
    ysync_kernel<<<yg, 512, YSM_TOTAL>>>(Woutb, all_y);
}

// round 17
// speedup vs baseline: 5.0842x; 1.0177x over previous
#include <cuda_runtime.h>
#include <cuda_bf16.h>
#include <cuda_fp16.h>
#include <cstdint>

// Problem constants
#define TT 256
#define BB 64
#define EE 512
#define HH 1024
#define VV 10000
#define G4 4096      // 4*H
#define NCTA 128
#define NTHR 512

// gx-GEMM tiling (proven R15)
#define NPAD2 10240           // VV padded to multiple of 256
#define YST 30720             // gxsync: bytes/stage (A 128x80 + B 256x80)
#define YSM_TOTAL (4 * YST)   // 120 KB

// ysync v2 tiling: CTA 64m x 256n, 16 warps (m4 x n4 of 16x64), 3 stages, 2 CTA/SM
#define Y2ST 25600            // A 64x80 + B 256x80
#define Y2SM (3 * Y2ST)       // 76800

// Persistent-recurrence smem layout (bytes)
#define RST 2064
#define R_HSM   0                       // h slab: 64 rows x 2048B (+pad)
#define R_WSM   (64 * RST)              // W tile: 32 rows x 2048B (+pad)
#define R_GSM   (R_WSM + 32 * RST)      // fp32 partials [2][64][32]
#define R_SHP   (R_GSM + 2 * 64 * 32 * 4)
#define R_GXS   (R_SHP + 16)            // gx prefetch buffer [64][32] fp32 = 8KB
#define RSM_TOTAL (R_GXS + 8192)        // ~222.8 KB

// Scratch (no cudaMalloc allowed): device globals
__device__ float g_gx  [(size_t)TT * BB * G4];            // [T*B][4H] fp32  256 MB
__device__ unsigned g_bar_count;
__device__ unsigned g_bar_phase;
__device__ __half g_xh[(size_t)TT * BB * EE];             // fp16 x_emb      16.8 MB
__device__ __half g_wx[(size_t)G4 * EE];                  // fp16 W_x^T      4 MB
__device__ float  g_gbias[G4];                            // packed gate bias
__device__ __half g_ah[(size_t)TT * BB * HH];             // fp16(all_h)     33.5 MB
__device__ __half g_h0h[(size_t)BB * HH];                 // fp16(h0)
__device__ __half g_wh[(size_t)G4 * HH];                  // fp16 packed W_h^T  8 MB
__device__ __half g_bh[(size_t)NPAD2 * HH];               // fp16(Wout^T)    21 MB

// ===========================================================================
// Helpers
// ===========================================================================
__device__ __forceinline__ uint32_t smem_to_u32(const void* p) {
    uint32_t a;
    asm("{ .reg .u64 t; cvta.to.shared.u64 t, %1; cvt.u32.u64 %0, t; }"
        : "=r"(a) : "l"(p));
    return a;
}
__device__ __forceinline__ void cp16(uint32_t dst, const void* src) {
    asm volatile("cp.async.cg.shared.global [%0], [%1], 16;\n"
                 :: "r"(dst), "l"(src) : "memory");
}
__device__ __forceinline__ void ldsm4(uint32_t& r0, uint32_t& r1,
                                      uint32_t& r2, uint32_t& r3, uint32_t a) {
    asm volatile("ldmatrix.sync.aligned.m8n8.x4.shared.b16 {%0,%1,%2,%3}, [%4];"
                 : "=r"(r0), "=r"(r1), "=r"(r2), "=r"(r3) : "r"(a));
}
__device__ __forceinline__ void hmma16(float* d, const uint32_t* a, const uint32_t* b) {
    asm volatile("mma.sync.aligned.m16n8k16.row.col.f32.f16.f16.f32 "
                 "{%0,%1,%2,%3}, {%4,%5,%6,%7}, {%8,%9}, {%0,%1,%2,%3};"
                 : "+f"(d[0]), "+f"(d[1]), "+f"(d[2]), "+f"(d[3])
                 : "r"(a[0]), "r"(a[1]), "r"(a[2]), "r"(a[3]),
                   "r"(b[0]), "r"(b[1]));
}
__device__ __forceinline__ float sigmoidf_(float x) {
    return 1.0f / (1.0f + __expf(-x));
}

// ---------------------------------------------------------------------------
// Kernel 1: embedding gather -> fp16 directly
// ---------------------------------------------------------------------------
__global__ void embed_kernel(const int* __restrict__ x, const float* __restrict__ emb) {
    int row = blockIdx.x;
    int idx = x[row];
    const float4* src = (const float4*)(emb + (size_t)idx * EE);
    float4 v = src[threadIdx.x];
    __half2 h0 = __floats2half2_rn(v.x, v.y);
    __half2 h1 = __floats2half2_rn(v.z, v.w);
    uint2* dst = (uint2*)(g_xh + (size_t)row * EE);
    uint2 pk;
    pk.x = *(uint32_t*)&h0;
    pk.y = *(uint32_t*)&h1;
    dst[threadIdx.x] = pk;
}

// ---------------------------------------------------------------------------
// Kernel 2a: transpose + convert W_x (rows [H,H+E)) -> g_wx[4H][E] fp16
// ---------------------------------------------------------------------------
__global__ void __launch_bounds__(256)
wgxconv_kernel(const float* __restrict__ Wf, const float* __restrict__ Wi,
               const float* __restrict__ Wc, const float* __restrict__ Wo) {
    __shared__ float t[32][33];
    const int gate = blockIdx.z;
    const float* W = (gate == 0) ? Wf : (gate == 1) ? Wi : (gate == 2) ? Wc : Wo;
    int k0 = blockIdx.x * 32, n0 = blockIdx.y * 32;
    int tx = threadIdx.x, ty = threadIdx.y;
#pragma unroll
    for (int j = 0; j < 4; ++j) {
        int k = k0 + ty + j * 8;
        t[ty + j * 8][tx] = W[(size_t)(HH + k) * HH + n0 + tx];
    }
    __syncthreads();
#pragma unroll
    for (int j = 0; j < 4; ++j) {
        int n = n0 + ty + j * 8;
        int k = k0 + tx;
        g_wx[(size_t)(gate * HH + n) * EE + k] = __float2half(t[tx][ty + j * 8]);
    }
}

// Kernel 2b: transpose + convert W_h (rows [0,H)) -> g_wh packed fp16
__global__ void __launch_bounds__(256)
whconv_kernel(const float* __restrict__ Wf, const float* __restrict__ Wi,
              const float* __restrict__ Wc, const float* __restrict__ Wo) {
    __shared__ float t[32][33];
    const int gate = blockIdx.z;
    const float* W = (gate == 0) ? Wf : (gate == 1) ? Wi : (gate == 2) ? Wc : Wo;
    int k0 = blockIdx.x * 32, j0 = blockIdx.y * 32;
    int tx = threadIdx.x, ty = threadIdx.y;
#pragma unroll
    for (int jj = 0; jj < 4; ++jj) {
        int k = k0 + ty + jj * 8;
        t[ty + jj * 8][tx] = W[(size_t)k * HH + j0 + tx];
    }
    __syncthreads();
#pragma unroll
    for (int jj = 0; jj < 4; ++jj) {
        int j = j0 + ty + jj * 8;
        int k = k0 + tx;
        int p = ((j >> 3) << 5) + gate * 8 + (j & 7);
        g_wh[(size_t)p * HH + k] = __float2half(t[tx][ty + jj * 8]);
    }
}

// Kernel 2c: pack gate biases
__global__ void bias_pack_kernel(const float* __restrict__ bf, const float* __restrict__ bi,
                                 const float* __restrict__ bc, const float* __restrict__ bo) {
    int n = blockIdx.x * 256 + threadIdx.x;
    int gate = n >> 10, j = n & (HH - 1);
    const float* b = (gate == 0) ? bf : (gate == 1) ? bi : (gate == 2) ? bc : bo;
    g_gbias[n] = b[j];
}

// Kernel 2d: h0 -> fp16
__global__ void h0conv_kernel(const float* __restrict__ h0) {
    int i = blockIdx.x * 256 + threadIdx.x;
    g_h0h[i] = __float2half(h0[i]);
}

// ---------------------------------------------------------------------------
// Kernel 3: fp16 HMMA gx-GEMM  g_gx = x_emb @ W_x^T + bias  (proven R15)
// ---------------------------------------------------------------------------
__device__ __forceinline__ void gx_fill(uint32_t sb, int stage, int m0, int n0,
                                        int kb, int tid) {
    uint32_t tb = sb + stage * YST;
    {
        int row = tid >> 2;
        int ch  = tid & 3;
        cp16(tb + row * 80 + ch * 16,
             g_xh + (size_t)(m0 + row) * EE + kb + ch * 8);
    }
#pragma unroll
    for (int i = 0; i < 2; ++i) {
        int idx = tid + i * 512;
        int row = idx >> 2;
        int ch  = idx & 3;
        cp16(tb + 10240 + row * 80 + ch * 16,
             g_wx + (size_t)(n0 + row) * EE + kb + ch * 8);
    }
    asm volatile("cp.async.commit_group;" ::: "memory");
}

__global__ void __launch_bounds__(512, 1)
gxsync_kernel() {
    extern __shared__ char ysm[];
    uint32_t sb = smem_to_u32(ysm);
    const int tid = threadIdx.x;
    const int lane = tid & 31;
    const int wid = tid >> 5;
    const int wm = wid & 1;
    const int wn = wid >> 1;
    const int n0 = blockIdx.x * 256;
    const int m0 = blockIdx.y * 128;

    const int lrow = lane & 7;
    const int sub  = lane >> 3;
    const int r16  = (sub & 1) * 8 + lrow;
    const int kby  = (sub >> 1) * 16;

    float acc[4][4][4];
#pragma unroll
    for (int a = 0; a < 4; ++a)
#pragma unroll
        for (int b = 0; b < 4; ++b)
#pragma unroll
            for (int d = 0; d < 4; ++d) acc[a][b][d] = 0.0f;

    gx_fill(sb, 0, m0, n0, 0,  tid);
    gx_fill(sb, 1, m0, n0, 32, tid);
    gx_fill(sb, 2, m0, n0, 64, tid);

#pragma unroll 1
    for (int it = 0; it < 16; ++it) {
        if (it < 14)       asm volatile("cp.async.wait_group 2;" ::: "memory");
        else if (it == 14) asm volatile("cp.async.wait_group 1;" ::: "memory");
        else               asm volatile("cp.async.wait_group 0;" ::: "memory");
        __syncthreads();

        uint32_t tb = sb + (it & 3) * YST;

#pragma unroll
        for (int ks = 0; ks < 2; ++ks) {
            uint32_t ah[4][4], bf2[4][2];
#pragma unroll
            for (int mf = 0; mf < 4; ++mf) {
                uint32_t ab = tb + (uint32_t)(wm * 64 + mf * 16 + r16) * 80
                            + ks * 32 + kby;
                ldsm4(ah[mf][0], ah[mf][1], ah[mf][2], ah[mf][3], ab);
            }
#pragma unroll
            for (int nf = 0; nf < 2; ++nf) {
                uint32_t bb = tb + 10240
                            + (uint32_t)(wn * 32 + nf * 16 + r16) * 80
                            + ks * 32 + kby;
                uint32_t r0, r1, r2, r3;
                ldsm4(r0, r1, r2, r3, bb);
                bf2[2 * nf][0] = r0;      bf2[2 * nf][1] = r2;
                bf2[2 * nf + 1][0] = r1;  bf2[2 * nf + 1][1] = r3;
            }
#pragma unroll
            for (int mf = 0; mf < 4; ++mf)
#pragma unroll
                for (int nb = 0; nb < 4; ++nb)
                    hmma16(acc[mf][nb], ah[mf], bf2[nb]);
        }

        if (it + 3 < 16) gx_fill(sb, (it + 3) & 3, m0, n0, (it + 3) * 32, tid);
    }

    const int g  = lane >> 2;
    const int i2 = (lane & 3) * 2;
#pragma unroll
    for (int mf = 0; mf < 4; ++mf) {
        int r0 = m0 + wm * 64 + mf * 16 + g;
#pragma unroll
        for (int nb = 0; nb < 4; ++nb) {
            int cc = n0 + wn * 32 + nb * 8 + i2;
            float b0 = g_gbias[cc], b1 = g_gbias[cc + 1];
            float2 v0 = make_float2(acc[mf][nb][0] + b0, acc[mf][nb][1] + b1);
            *(float2*)(g_gx + (size_t)r0 * G4 + cc) = v0;
            float2 v1 = make_float2(acc[mf][nb][2] + b0, acc[mf][nb][3] + b1);
            *(float2*)(g_gx + (size_t)(r0 + 8) * G4 + cc) = v1;
        }
    }
}

// ---------------------------------------------------------------------------
// Kernel 4: persistent LSTM recurrence — fp16 HMMA mainloop + gx smem prefetch
// ---------------------------------------------------------------------------
__device__ __forceinline__ void grid_bar(unsigned target) {
    __syncthreads();
    if (threadIdx.x == 0) {
        __threadfence();
        unsigned old = atomicAdd(&g_bar_count, 1u);
        if (old == NCTA - 1) {
            atomicExch(&g_bar_count, 0u);
            __threadfence();
            atomicAdd(&g_bar_phase, 1u);
        } else {
            while ((int)(*((volatile unsigned*)&g_bar_phase) - target) < 0) {}
            __threadfence();
        }
    }
    __syncthreads();
}

__global__ void __launch_bounds__(NTHR, 1)
lstm_persistent_kernel(const float* __restrict__ c0,
                       float* __restrict__ all_h, float* __restrict__ all_c) {
    extern __shared__ char rsm[];
    uint32_t sb = smem_to_u32(rsm);
    const uint32_t hsm = sb + R_HSM;
    const uint32_t wsm = sb + R_WSM;
    float* gsm = (float*)(rsm + R_GSM);          // [2][64][32]
    unsigned* shp = (unsigned*)(rsm + R_SHP);
    float* gxs = (float*)(rsm + R_GXS);          // [64][32]
    const uint32_t gxsm = sb + R_GXS;

    const int tid = threadIdx.x;
    const int lane = tid & 31;
    const int wid = tid >> 5;
    const int mw   = wid & 3;          // m-tile (16 rows)
    const int nw16 = (wid >> 2) & 1;   // n-tile (16 packed cols)
    const int ksw  = wid >> 3;         // K-half
    const int n    = blockIdx.x;       // CTA: H-cols [n*8, n*8+8)

    const int lrow = lane & 7;
    const int sub  = lane >> 3;
    const int r16  = (sub & 1) * 8 + lrow;
    const int kby  = (sub >> 1) * 16;

    // ---- load W tile once (32 rows x 2048B)
#pragma unroll
    for (int q = 0; q < 8; ++q) {
        int idx = tid + q * NTHR;
        int row = idx >> 7;
        int ch  = idx & 127;
        cp16(wsm + row * RST + ch * 16,
             g_wh + (size_t)(n * 32 + row) * HH + ch * 8);
    }
    asm volatile("cp.async.commit_group;\n" ::: "memory");

    // ---- cell-thread state: thread (m = tid>>3, jo = tid&7)
    const int cm = tid >> 3;
    const int cj = tid & 7;
    const size_t coff = (size_t)cm * HH + n * 8 + cj;
    float c_reg = c0[coff];

    if (tid == 0) shp[0] = *((volatile unsigned*)&g_bar_phase);
    asm volatile("cp.async.wait_group 0;\n" ::: "memory");
    __syncthreads();
    const unsigned phase_base = shp[0];

    // gx prefetch indices (one cp16 per thread)
    const int px_row  = tid >> 3;
    const int px_gate = (tid >> 1) & 3;
    const int px_part = tid & 1;
    const uint32_t px_dst = gxsm + px_row * 128 + px_gate * 32 + px_part * 16;

    for (int t = 0; t < TT; ++t) {
        const __half* hsrc = (t == 0) ? g_h0h : g_ah + (size_t)(t - 1) * BB * HH;

        // ---- group 1: h slab (64 rows x 2048B fp16)
#pragma unroll
        for (int q = 0; q < 16; ++q) {
            int idx = tid + q * NTHR;
            int row = idx >> 7;
            int ch  = idx & 127;
            cp16(hsm + row * RST + ch * 16,
                 hsrc + (size_t)row * HH + ch * 8);
        }
        asm volatile("cp.async.commit_group;\n" ::: "memory");
        // ---- group 2: gx slice for this step (8KB)
        cp16(px_dst, g_gx + ((size_t)t * BB + px_row) * G4
                     + px_gate * HH + n * 8 + px_part * 4);
        asm volatile("cp.async.commit_group;\n" ::: "memory");

        asm volatile("cp.async.wait_group 1;\n" ::: "memory");   // h done, gx may pend
        __syncthreads();

        // ---- mma: 16x16 tile per warp over K-half 512
        float acc[2][4];
#pragma unroll
        for (int a = 0; a < 2; ++a)
#pragma unroll
            for (int d = 0; d < 4; ++d) acc[a][d] = 0.0f;

        const uint32_t abase = hsm + (uint32_t)(mw * 16 + r16) * RST + ksw * 1024 + kby;
        const uint32_t bbase = wsm + (uint32_t)(nw16 * 16 + r16) * RST + ksw * 1024 + kby;
#pragma unroll 4
        for (int ki = 0; ki < 32; ++ki) {
            uint32_t a0, a1, a2, a3, r0, r1, r2, r3;
            ldsm4(a0, a1, a2, a3, abase + ki * 32);
            ldsm4(r0, r1, r2, r3, bbase + ki * 32);
            uint32_t af[4] = {a0, a1, a2, a3};
            uint32_t b0[2] = {r0, r2};
            uint32_t b1[2] = {r1, r3};
            hmma16(acc[0], af, b0);
            hmma16(acc[1], af, b1);
        }

        // ---- write partials to gsm[ks][m][packed col]
        {
            int row = lane >> 2;
            int col = (lane & 3) * 2;
            float* base = gsm + ksw * 2048 + (mw * 16 + row) * 32 + nw16 * 16 + col;
            base[0] = acc[0][0];          base[1] = acc[0][1];
            base[8 * 32] = acc[0][2];     base[8 * 32 + 1] = acc[0][3];
            base[8] = acc[1][0];          base[9] = acc[1][1];
            base[8 * 32 + 8] = acc[1][2]; base[8 * 32 + 9] = acc[1][3];
        }
        asm volatile("cp.async.wait_group 0;\n" ::: "memory");   // gx done
        __syncthreads();

        // ---- cell (c in register, gx from smem)
        {
            const float* g0 = gsm + cm * 32;
            const float* g1 = gsm + 2048 + cm * 32;
            const float* gx = gxs + cm * 32;
            float gf = g0[cj]      + g1[cj]      + gx[cj];
            float gi = g0[8 + cj]  + g1[8 + cj]  + gx[8 + cj];
            float gc = g0[16 + cj] + g1[16 + cj] + gx[16 + cj];
            float go = g0[24 + cj] + g1[24 + cj] + gx[24 + cj];
            float f  = sigmoidf_(gf);
            float ii = sigmoidf_(gi);
            float cd = tanhf(gc);
            float o  = sigmoidf_(go);
            c_reg = f * c_reg + ii * cd;
            size_t off = (size_t)t * BB * HH + coff;
            all_c[off] = c_reg;
            float hv = o * tanhf(c_reg);
            all_h[off] = hv;
            g_ah[off] = __float2half(hv);
        }

        grid_bar(phase_base + (unsigned)t + 1u);
    }
}

// ---------------------------------------------------------------------------
// Kernel 5: transpose + convert Wout [K][V] -> g_bh [NPAD2][K] fp16 (zero-pad)
// ---------------------------------------------------------------------------
__global__ void __launch_bounds__(256)
wconv_kernel(const float* __restrict__ W) {
    __shared__ float t[32][33];
    int k0 = blockIdx.x * 32, n0 = blockIdx.y * 32;
    int tx = threadIdx.x, ty = threadIdx.y;
#pragma unroll
    for (int j = 0; j < 4; ++j) {
        int k = k0 + ty + j * 8, n = n0 + tx;
        t[ty + j * 8][tx] = (n < VV) ? W[(size_t)k * VV + n] : 0.0f;
    }
    __syncthreads();
#pragma unroll
    for (int j = 0; j < 4; ++j) {
        int n = n0 + ty + j * 8, k = k0 + tx;
        g_bh[(size_t)n * HH + k] = __float2half(t[tx][ty + j * 8]);
    }
}

// ---------------------------------------------------------------------------
// Kernel 6: fp16 y-GEMM v2 — CTA 64x256, warp 16x64, 3 stages, 2 CTAs/SM
// ---------------------------------------------------------------------------
__device__ __forceinline__ void y2_fill(uint32_t sb, int slot, int m0, int n0,
                                        int kb, int tid) {
    uint32_t tb = sb + slot * Y2ST;
#pragma unroll
    for (int i = 0; i < 3; ++i) {
        int idx = tid + i * 512;              // 0..1535
        if (idx < 256) {
            int row = idx >> 2, ch = idx & 3;
            cp16(tb + row * 80 + ch * 16,
                 g_ah + (size_t)(m0 + row) * HH + kb + ch * 8);
        } else if (idx < 1280) {
            int j = idx - 256;
            int row = j >> 2, ch = j & 3;
            cp16(tb + 5120 + row * 80 + ch * 16,
                 g_bh + (size_t)(n0 + row) * HH + kb + ch * 8);
        }
    }
    asm volatile("cp.async.commit_group;" ::: "memory");
}

__global__ void __launch_bounds__(512, 2)
ysync_kernel(const float* __restrict__ bout, float* __restrict__ Y) {
    extern __shared__ char ysm[];
    uint32_t sb = smem_to_u32(ysm);
    const int tid = threadIdx.x;
    const int lane = tid & 31;
    const int wid = tid >> 5;
    const int wm = wid & 3;               // m16 tile
    const int wn = wid >> 2;              // n64 tile (0..3)
    const int n0 = blockIdx.x * 256;
    const int m0 = blockIdx.y * 64;

    const int lrow = lane & 7;
    const int sub  = lane >> 3;
    const int r16  = (sub & 1) * 8 + lrow;
    const int kby  = (sub >> 1) * 16;

    float acc[8][4];
#pragma unroll
    for (int b = 0; b < 8; ++b)
#pragma unroll
        for (int d = 0; d < 4; ++d) acc[b][d] = 0.0f;

    y2_fill(sb, 0, m0, n0, 0,  tid);
    y2_fill(sb, 1, m0, n0, 32, tid);

    int slot = 0;
#pragma unroll 1
    for (int it = 0; it < 32; ++it) {
        if (it < 31) asm volatile("cp.async.wait_group 1;" ::: "memory");
        else         asm volatile("cp.async.wait_group 0;" ::: "memory");
        __syncthreads();

        uint32_t tb = sb + slot * Y2ST;

#pragma unroll
        for (int ks = 0; ks < 2; ++ks) {
            uint32_t a0, a1, a2, a3;
            ldsm4(a0, a1, a2, a3,
                  tb + (uint32_t)(wm * 16 + r16) * 80 + ks * 32 + kby);
            uint32_t af[4] = {a0, a1, a2, a3};
#pragma unroll
            for (int nf = 0; nf < 4; ++nf) {
                uint32_t r0, r1, r2, r3;
                ldsm4(r0, r1, r2, r3,
                      tb + 5120 + (uint32_t)(wn * 64 + nf * 16 + r16) * 80
                      + ks * 32 + kby);
                uint32_t b0[2] = {r0, r2};
                uint32_t b1[2] = {r1, r3};
                hmma16(acc[2 * nf],     af, b0);
                hmma16(acc[2 * nf + 1], af, b1);
            }
        }

        if (it + 2 < 32) {
            int pf = slot;   // slot being refilled = (it+2)%3 == current slot's successor-of-successor
            pf = slot + 2; if (pf >= 3) pf -= 3;
            y2_fill(sb, pf, m0, n0, (it + 2) * 32, tid);
        }
        slot = (slot == 2) ? 0 : slot + 1;
    }

    // Epilogue: direct stores + bias
    const int g  = lane >> 2;
    const int i2 = (lane & 3) * 2;
    int r0 = m0 + wm * 16 + g;
#pragma unroll
    for (int nb = 0; nb < 8; ++nb) {
        int cc = n0 + wn * 64 + nb * 8 + i2;
        if (cc < VV) {
            float b0 = bout[cc], b1 = bout[cc + 1];
            float2 v0 = make_float2(acc[nb][0] + b0, acc[nb][1] + b1);
            *(float2*)(Y + (size_t)r0 * VV + cc) = v0;
            float2 v1 = make_float2(acc[nb][2] + b0, acc[nb][3] + b1);
            *(float2*)(Y + (size_t)(r0 + 8) * VV + cc) = v1;
        }
    }
}

// ---------------------------------------------------------------------------
// Launch
// ---------------------------------------------------------------------------
extern "C" void kernel_launch(void* const* d_in, const int* in_sizes, int n_in,
                              void* d_out, int out_size) {
    const int*   x     = (const int*)d_in[0];
    const float* h0    = (const float*)d_in[1];
    const float* c0    = (const float*)d_in[2];
    const float* emb   = (const float*)d_in[3];
    const float* Wf_w  = (const float*)d_in[4];
    const float* Wf_b  = (const float*)d_in[5];
    const float* Wi_w  = (const float*)d_in[6];
    const float* Wi_b  = (const float*)d_in[7];
    const float* Wc_w  = (const float*)d_in[8];
    const float* Wc_b  = (const float*)d_in[9];
    const float* Wo_w  = (const float*)d_in[10];
    const float* Wo_b  = (const float*)d_in[11];
    const float* Woutw = (const float*)d_in[12];
    const float* Woutb = (const float*)d_in[13];

    float* out   = (float*)d_out;
    float* all_h = out;
    float* all_c = out + (size_t)TT * BB * HH;
    float* all_y = out + (size_t)2 * TT * BB * HH;

    cudaFuncSetAttribute(lstm_persistent_kernel,
                         cudaFuncAttributeMaxDynamicSharedMemorySize, RSM_TOTAL);
    cudaFuncSetAttribute(ysync_kernel,
                         cudaFuncAttributeMaxDynamicSharedMemorySize, Y2SM);
    cudaFuncSetAttribute(gxsync_kernel,
                         cudaFuncAttributeMaxDynamicSharedMemorySize, YSM_TOTAL);

    // 1) gather embeddings -> fp16
    embed_kernel<<<TT * BB, 128>>>(x, emb);

    // 2) prep: weight transposes/conversions, bias pack, h0 conversion
    dim3 wxg(EE / 32, HH / 32, 4);
    wgxconv_kernel<<<wxg, dim3(32, 8)>>>(Wf_w, Wi_w, Wc_w, Wo_w);
    dim3 whg(HH / 32, HH / 32, 4);
    whconv_kernel<<<whg, dim3(32, 8)>>>(Wf_w, Wi_w, Wc_w, Wo_w);
    bias_pack_kernel<<<G4 / 256, 256>>>(Wf_b, Wi_b, Wc_b, Wo_b);
    h0conv_kernel<<<(BB * HH) / 256, 256>>>(h0);
    dim3 wsg(HH / 32, NPAD2 / 32);
    wconv_kernel<<<wsg, dim3(32, 8)>>>(Woutw);

    // 3) gx = x_emb @ W_x^T + bias  (fp16 HMMA)
    dim3 gxg(G4 / 256, (TT * BB) / 128);   // 16 x 128
    gxsync_kernel<<<gxg, 512, YSM_TOTAL>>>();

    // 4) recurrence (persistent, fp16 HMMA mainloop, gx smem prefetch)
    lstm_persistent_kernel<<<NCTA, NTHR, RSM_TOTAL>>>(c0, all_h, all_c);

    // 5) y-projection v2 (fp16 mma.sync, 2 CTAs/SM)
    dim3 yg(NPAD2 / 256, (TT * BB) / 64);   // 40 x 256
    ysync_kernel<<<yg, 512, Y2SM>>>(Woutb, all_y);
}